// round 1
// baseline (speedup 1.0000x reference)
#include <cuda_runtime.h>
#include <math.h>

#define Bc 4
#define Tc 2048
#define Cc 2048
#define Hc 128
#define Ec 16
#define Nc (Bc*Tc)
#define GT 4   // tokens per gating block

// ---------------- device scratch (no allocations allowed) ----------------
__device__ float g_q[Nc*Hc];
__device__ float g_k[Nc*Hc];
__device__ float g_v[Nc*Hc];
__device__ float g_attn[Nc*Hc];
__device__ int   g_cnt[Ec];
__device__ int   g_tok[Ec*Nc];
__device__ float g_w[Ec*Nc];
__device__ float g_wninv[Ec];
__device__ float g_sig[Ec];

// ---------------- zero scratch + output ----------------
__global__ void k_zero(float* __restrict__ out) {
    int i = blockIdx.x * blockDim.x + threadIdx.x;
    int stride = gridDim.x * blockDim.x;
    float4 z = make_float4(0.f, 0.f, 0.f, 0.f);
    for (int j = i; j < Nc*Cc/4; j += stride) ((float4*)out)[j] = z;
    for (int j = i; j < Nc*Hc/4; j += stride) {
        ((float4*)g_q)[j] = z;
        ((float4*)g_k)[j] = z;
        ((float4*)g_v)[j] = z;
    }
    if (i < Ec) g_cnt[i] = 0;
}

// ---------------- prep: sim column norms + sigmoid(gates) ----------------
__global__ void k_prep(const float* __restrict__ sim, const float* __restrict__ gates) {
    int w = threadIdx.x >> 5, lane = threadIdx.x & 31;   // 16 warps, warp w -> expert w
    float s = 0.f;
    for (int i = lane; i < Cc; i += 32) {
        float v = sim[(size_t)i*Ec + w];
        s += v*v;
    }
    #pragma unroll
    for (int o = 16; o; o >>= 1) s += __shfl_xor_sync(0xffffffffu, s, o);
    if (lane == 0) g_wninv[w] = 1.0f / fmaxf(sqrtf(s), 1e-12f);
    if (threadIdx.x < Ec) g_sig[threadIdx.x] = 1.0f / (1.0f + expf(-gates[threadIdx.x]));
}

// ---------------- gating: logits, relu/STE, top-2 fallback, softmax, lists ----------------
__global__ void k_gate(const float* __restrict__ x, const float* __restrict__ sim) {
    int n0 = blockIdx.x * GT;
    float dot[GT][Ec];
    float ss[GT];
    #pragma unroll
    for (int j = 0; j < GT; j++) {
        ss[j] = 0.f;
        #pragma unroll
        for (int e = 0; e < Ec; e++) dot[j][e] = 0.f;
    }
    for (int i = threadIdx.x; i < Cc; i += 256) {
        float xv[GT];
        #pragma unroll
        for (int j = 0; j < GT; j++) {
            xv[j] = x[(size_t)(n0 + j)*Cc + i];
            ss[j] += xv[j]*xv[j];
        }
        const float4* s4 = (const float4*)(sim + (size_t)i*Ec);
        #pragma unroll
        for (int q = 0; q < 4; q++) {
            float4 sv = s4[q];
            #pragma unroll
            for (int j = 0; j < GT; j++) {
                dot[j][q*4+0] += xv[j]*sv.x;
                dot[j][q*4+1] += xv[j]*sv.y;
                dot[j][q*4+2] += xv[j]*sv.z;
                dot[j][q*4+3] += xv[j]*sv.w;
            }
        }
    }
    __shared__ float red[8][GT*Ec + GT];
    int wid = threadIdx.x >> 5, lane = threadIdx.x & 31;
    #pragma unroll
    for (int j = 0; j < GT; j++) {
        #pragma unroll
        for (int e = 0; e < Ec; e++) {
            float v = dot[j][e];
            #pragma unroll
            for (int o = 16; o; o >>= 1) v += __shfl_xor_sync(0xffffffffu, v, o);
            if (lane == 0) red[wid][j*Ec + e] = v;
        }
        float v = ss[j];
        #pragma unroll
        for (int o = 16; o; o >>= 1) v += __shfl_xor_sync(0xffffffffu, v, o);
        if (lane == 0) red[wid][GT*Ec + j] = v;
    }
    __syncthreads();
    if (threadIdx.x < GT*Ec + GT) {
        float s = 0.f;
        #pragma unroll
        for (int w = 0; w < 8; w++) s += red[w][threadIdx.x];
        red[0][threadIdx.x] = s;
    }
    __syncthreads();
    if (threadIdx.x < GT) {
        int j = threadIdx.x;
        int n = n0 + j;
        float xin = rsqrtf(fmaxf(red[0][GT*Ec + j], 1e-24f));   // 1/max(||x||,1e-12)
        float logitv[Ec], gatedv[Ec];
        int act = 0;
        #pragma unroll
        for (int e = 0; e < Ec; e++) {
            float lg = red[0][j*Ec + e] * xin * g_wninv[e] - g_sig[e];
            logitv[e] = lg;
            gatedv[e] = fmaxf(lg, 0.f);
            act += (lg > 0.f) ? 1 : 0;
        }
        unsigned mask = 0u;
        if (act > 0) {
            #pragma unroll
            for (int e = 0; e < Ec; e++) if (logitv[e] > 0.f) mask |= (1u << e);
        } else {
            int i1 = 0;
            #pragma unroll
            for (int e = 1; e < Ec; e++) if (logitv[e] > logitv[i1]) i1 = e;
            int i2 = (i1 == 0) ? 1 : 0;
            #pragma unroll
            for (int e = 0; e < Ec; e++)
                if (e != i1 && logitv[e] > logitv[i2]) i2 = e;
            mask = (1u << i1) | (1u << i2);
        }
        float m = -1e30f;
        #pragma unroll
        for (int e = 0; e < Ec; e++) if ((mask >> e) & 1u) m = fmaxf(m, gatedv[e]);
        float ssum = 0.f;
        float ex[Ec];
        #pragma unroll
        for (int e = 0; e < Ec; e++) {
            float t = ((mask >> e) & 1u) ? expf(gatedv[e] - m) : 0.f;
            ex[e] = t;
            ssum += t;
        }
        float sinv = 1.f / ssum;
        #pragma unroll
        for (int e = 0; e < Ec; e++) {
            if ((mask >> e) & 1u) {
                int p = atomicAdd(&g_cnt[e], 1);
                g_tok[e*Nc + p] = n;
                g_w[e*Nc + p]   = ex[e] * sinv;
            }
        }
    }
}

// ---------------- grouped GEMM: q/k/v = w * x @ proj[e] ----------------
__global__ __launch_bounds__(256) void k_qkv(const float* __restrict__ x,
                                             const float* __restrict__ qp,
                                             const float* __restrict__ kp,
                                             const float* __restrict__ vp) {
    int e = blockIdx.y;
    int cnt = g_cnt[e];
    int m0 = blockIdx.x * 64;
    if (m0 >= cnt) return;
    const float* proj;
    float* dst;
    if (blockIdx.z == 0)      { proj = qp; dst = g_q; }
    else if (blockIdx.z == 1) { proj = kp; dst = g_k; }
    else                      { proj = vp; dst = g_v; }

    __shared__ float As[32][64];     // transposed A chunk
    __shared__ float Bs[32][128];
    __shared__ int   sTok[64];
    __shared__ float sW[64];
    int tid = threadIdx.x;
    if (tid < 64) {
        int idx = m0 + tid;
        if (idx < cnt) { sTok[tid] = g_tok[e*Nc + idx]; sW[tid] = g_w[e*Nc + idx]; }
        else           { sTok[tid] = -1;                 sW[tid] = 0.f; }
    }
    __syncthreads();

    int ty = tid >> 4, tx = tid & 15;
    float acc[4][8];
    #pragma unroll
    for (int i = 0; i < 4; i++)
        #pragma unroll
        for (int jj = 0; jj < 8; jj++) acc[i][jj] = 0.f;

    int ar = tid >> 3;            // 0..31
    int ak = (tid & 7) * 4;
    int bk = tid >> 3;
    int bc = (tid & 7) * 16;

    for (int k0 = 0; k0 < Cc; k0 += 32) {
        #pragma unroll
        for (int p = 0; p < 2; p++) {
            int rr = ar + p*32;
            int tok = sTok[rr];
            float w = sW[rr];
            float4 xv = make_float4(0.f, 0.f, 0.f, 0.f);
            if (tok >= 0) xv = *(const float4*)(x + (size_t)tok*Cc + k0 + ak);
            As[ak+0][rr] = xv.x*w; As[ak+1][rr] = xv.y*w;
            As[ak+2][rr] = xv.z*w; As[ak+3][rr] = xv.w*w;
        }
        const float* src = proj + ((size_t)e*Cc + (k0 + bk))*Hc + bc;
        #pragma unroll
        for (int q = 0; q < 4; q++)
            *(float4*)&Bs[bk][bc + 4*q] = *(const float4*)(src + 4*q);
        __syncthreads();
        #pragma unroll
        for (int kk = 0; kk < 32; kk++) {
            float4 b0 = *(float4*)&Bs[kk][tx*8];
            float4 b1 = *(float4*)&Bs[kk][tx*8 + 4];
            #pragma unroll
            for (int i = 0; i < 4; i++) {
                float a = As[kk][ty*4 + i];
                acc[i][0] += a*b0.x; acc[i][1] += a*b0.y;
                acc[i][2] += a*b0.z; acc[i][3] += a*b0.w;
                acc[i][4] += a*b1.x; acc[i][5] += a*b1.y;
                acc[i][6] += a*b1.z; acc[i][7] += a*b1.w;
            }
        }
        __syncthreads();
    }
    #pragma unroll
    for (int i = 0; i < 4; i++) {
        int tok = sTok[ty*4 + i];
        if (tok < 0) continue;
        float* o = dst + (size_t)tok*Hc + tx*8;
        #pragma unroll
        for (int jj = 0; jj < 8; jj++) atomicAdd(o + jj, acc[i][jj]);
    }
}

// ---------------- RoPE in-place on g_q, g_k ----------------
__global__ void k_rope(const int* __restrict__ pid) {
    int idx = blockIdx.x * blockDim.x + threadIdx.x;    // Nc*64 threads
    if (idx >= Nc*64) return;
    int n = idx >> 6;
    int i = idx & 63;
    int t = pid[n & (Tc - 1)];
    // inv_freq = 10000^(-i/64)
    float ang = (float)t * exp2f(-(float)i * (13.28771237954945f / 64.0f));
    float s, c;
    sincosf(ang, &s, &c);
    size_t base = (size_t)n * Hc;
    float q0 = g_q[base + i], q1 = g_q[base + i + 64];
    g_q[base + i]      = q0*c - q1*s;
    g_q[base + i + 64] = q1*c + q0*s;
    float k0 = g_k[base + i], k1 = g_k[base + i + 64];
    g_k[base + i]      = k0*c - k1*s;
    g_k[base + i + 64] = k1*c + k0*s;
}

// ---------------- causal flash attention (single head, fp32) ----------------
__global__ __launch_bounds__(256) void k_attn() {
    int qt = blockIdx.x, b = blockIdx.y;
    int q0 = qt * 32;
    __shared__ float Qs[32][128];
    __shared__ float KVs[32][128];
    __shared__ float Ps[32][32];
    __shared__ float sM[32], sL[32];
    int tid = threadIdx.x;
    int row = tid >> 3;        // 0..31
    int cg  = tid & 7;         // 8 threads per row

    {
        const float* src = g_q + ((size_t)(b*Tc + q0 + row))*Hc + cg*16;
        #pragma unroll
        for (int j = 0; j < 4; j++)
            *(float4*)&Qs[row][cg*16 + 4*j] = *(const float4*)(src + 4*j);
    }
    if (tid < 32) { sM[tid] = -1e30f; sL[tid] = 0.f; }

    float accO[16];
    #pragma unroll
    for (int j = 0; j < 16; j++) accO[j] = 0.f;
    const float scale = 0.08838834764831845f;   // 1/sqrt(128)

    for (int kt = 0; kt <= qt; kt++) {
        int k0 = kt * 32;
        {
            const float* src = g_k + ((size_t)(b*Tc + k0 + row))*Hc + cg*16;
            #pragma unroll
            for (int j = 0; j < 4; j++)
                *(float4*)&KVs[row][cg*16 + 4*j] = *(const float4*)(src + 4*j);
        }
        __syncthreads();

        float s4a[4] = {0.f, 0.f, 0.f, 0.f};
        int cb = cg * 4;
        #pragma unroll 8
        for (int k4 = 0; k4 < 32; k4++) {
            float4 q4 = *(float4*)&Qs[row][k4*4];
            #pragma unroll
            for (int c = 0; c < 4; c++) {
                float4 kv = *(float4*)&KVs[cb + c][k4*4];
                s4a[c] += q4.x*kv.x + q4.y*kv.y + q4.z*kv.z + q4.w*kv.w;
            }
        }
        float sv[4];
        float mloc = -1e30f;
        #pragma unroll
        for (int c = 0; c < 4; c++) {
            int kpos = k0 + cb + c;
            sv[c] = (kpos <= q0 + row) ? s4a[c]*scale : -1e30f;
            mloc = fmaxf(mloc, sv[c]);
        }
        #pragma unroll
        for (int o = 1; o < 8; o <<= 1) mloc = fmaxf(mloc, __shfl_xor_sync(0xffffffffu, mloc, o));
        float mprev = sM[row];
        float mnew = fmaxf(mprev, mloc);
        float p[4];
        float ps = 0.f;
        #pragma unroll
        for (int c = 0; c < 4; c++) { p[c] = __expf(sv[c] - mnew); ps += p[c]; }
        #pragma unroll
        for (int o = 1; o < 8; o <<= 1) ps += __shfl_xor_sync(0xffffffffu, ps, o);
        float alpha = __expf(mprev - mnew);
        #pragma unroll
        for (int j = 0; j < 16; j++) accO[j] *= alpha;
        if (cg == 0) { sM[row] = mnew; sL[row] = sL[row]*alpha + ps; }
        #pragma unroll
        for (int c = 0; c < 4; c++) Ps[row][cb + c] = p[c];
        __syncthreads();
        {
            const float* src = g_v + ((size_t)(b*Tc + k0 + row))*Hc + cg*16;
            #pragma unroll
            for (int j = 0; j < 4; j++)
                *(float4*)&KVs[row][cg*16 + 4*j] = *(const float4*)(src + 4*j);
        }
        __syncthreads();
        #pragma unroll 4
        for (int kp = 0; kp < 32; kp++) {
            float pv = Ps[row][kp];
            #pragma unroll
            for (int j4 = 0; j4 < 4; j4++) {
                float4 v4 = *(float4*)&KVs[kp][cg*16 + 4*j4];
                accO[j4*4+0] += pv*v4.x; accO[j4*4+1] += pv*v4.y;
                accO[j4*4+2] += pv*v4.z; accO[j4*4+3] += pv*v4.w;
            }
        }
        __syncthreads();
    }
    float linv = 1.0f / sL[row];
    float* dst = g_attn + ((size_t)(b*Tc + q0 + row))*Hc + cg*16;
    #pragma unroll
    for (int j = 0; j < 16; j++) dst[j] = accO[j]*linv;
}

// ---------------- grouped GEMM: out += w * attn @ o_proj[e] ----------------
__global__ __launch_bounds__(256) void k_oproj(const float* __restrict__ op,
                                               float* __restrict__ out) {
    int e = blockIdx.y;
    int cnt = g_cnt[e];
    int m0 = blockIdx.x * 64;
    if (m0 >= cnt) return;
    int z = blockIdx.z;                 // output column tile: [z*128, z*128+128)

    __shared__ float As[32][64];
    __shared__ float Bs[32][128];
    __shared__ int   sTok[64];
    __shared__ float sW[64];
    int tid = threadIdx.x;
    if (tid < 64) {
        int idx = m0 + tid;
        if (idx < cnt) { sTok[tid] = g_tok[e*Nc + idx]; sW[tid] = g_w[e*Nc + idx]; }
        else           { sTok[tid] = -1;                 sW[tid] = 0.f; }
    }
    __syncthreads();

    int ty = tid >> 4, tx = tid & 15;
    float acc[4][8];
    #pragma unroll
    for (int i = 0; i < 4; i++)
        #pragma unroll
        for (int jj = 0; jj < 8; jj++) acc[i][jj] = 0.f;

    int ar = tid >> 3;
    int ak = (tid & 7) * 4;
    int bk = tid >> 3;
    int bc = (tid & 7) * 16;

    for (int k0 = 0; k0 < Hc; k0 += 32) {
        #pragma unroll
        for (int p = 0; p < 2; p++) {
            int rr = ar + p*32;
            int tok = sTok[rr];
            float w = sW[rr];
            float4 xv = make_float4(0.f, 0.f, 0.f, 0.f);
            if (tok >= 0) xv = *(const float4*)(g_attn + (size_t)tok*Hc + k0 + ak);
            As[ak+0][rr] = xv.x*w; As[ak+1][rr] = xv.y*w;
            As[ak+2][rr] = xv.z*w; As[ak+3][rr] = xv.w*w;
        }
        const float* src = op + ((size_t)e*Hc + (k0 + bk))*Cc + z*128 + bc;
        #pragma unroll
        for (int q = 0; q < 4; q++)
            *(float4*)&Bs[bk][bc + 4*q] = *(const float4*)(src + 4*q);
        __syncthreads();
        #pragma unroll
        for (int kk = 0; kk < 32; kk++) {
            float4 b0 = *(float4*)&Bs[kk][tx*8];
            float4 b1 = *(float4*)&Bs[kk][tx*8 + 4];
            #pragma unroll
            for (int i = 0; i < 4; i++) {
                float a = As[kk][ty*4 + i];
                acc[i][0] += a*b0.x; acc[i][1] += a*b0.y;
                acc[i][2] += a*b0.z; acc[i][3] += a*b0.w;
                acc[i][4] += a*b1.x; acc[i][5] += a*b1.y;
                acc[i][6] += a*b1.z; acc[i][7] += a*b1.w;
            }
        }
        __syncthreads();
    }
    #pragma unroll
    for (int i = 0; i < 4; i++) {
        int tok = sTok[ty*4 + i];
        if (tok < 0) continue;
        float* o = out + (size_t)tok*Cc + z*128 + tx*8;
        #pragma unroll
        for (int jj = 0; jj < 8; jj++) atomicAdd(o + jj, acc[i][jj]);
    }
}

// ---------------- launch ----------------
extern "C" void kernel_launch(void* const* d_in, const int* in_sizes, int n_in,
                              void* d_out, int out_size) {
    const float* x     = (const float*)d_in[0];
    const int*   pid   = (const int*)  d_in[1];
    const float* sim   = (const float*)d_in[2];
    const float* gates = (const float*)d_in[3];
    const float* qp    = (const float*)d_in[4];
    const float* kp    = (const float*)d_in[5];
    const float* vp    = (const float*)d_in[6];
    const float* op    = (const float*)d_in[7];
    float* out = (float*)d_out;

    k_zero <<<4096, 256>>>(out);
    k_prep <<<1, 512>>>(sim, gates);
    k_gate <<<Nc/GT, 256>>>(x, sim);
    k_qkv  <<<dim3(Nc/64, Ec, 3), 256>>>(x, qp, kp, vp);
    k_rope <<<(Nc*64)/256, 256>>>(pid);
    k_attn <<<dim3(Tc/32, Bc), 256>>>();
    k_oproj<<<dim3(Nc/64, Ec, 16), 256>>>(op, out);
}

// round 2
// speedup vs baseline: 1.1110x; 1.1110x over previous
#include <cuda_runtime.h>
#include <math.h>

#define Bc 4
#define Tc 2048
#define Cc 2048
#define Hc 128
#define Ec 16
#define Nc (Bc*Tc)
#define GT 4   // tokens per gating block

// ---------------- device scratch (no allocations allowed) ----------------
__device__ float g_q[Nc*Hc];
__device__ float g_k[Nc*Hc];
__device__ float g_v[Nc*Hc];
__device__ float g_attn[Nc*Hc];
__device__ int   g_cnt[Ec];
__device__ int   g_tok[Ec*Nc];
__device__ float g_w[Ec*Nc];
__device__ float g_wninv[Ec];
__device__ float g_sig[Ec];

// ---------------- f32x2 packed helpers (sm_103a) ----------------
__device__ __forceinline__ unsigned long long pack2(float lo, float hi) {
    unsigned long long r;
    asm("mov.b64 %0,{%1,%2};" : "=l"(r) : "f"(lo), "f"(hi));
    return r;
}
__device__ __forceinline__ void ffma2(unsigned long long& d, unsigned long long a, unsigned long long b) {
    asm("fma.rn.f32x2 %0,%1,%2,%0;" : "+l"(d) : "l"(a), "l"(b));
}
__device__ __forceinline__ void unpack2(unsigned long long v, float& lo, float& hi) {
    asm("mov.b64 {%0,%1},%2;" : "=f"(lo), "=f"(hi) : "l"(v));
}

// ---------------- zero scratch + output ----------------
__global__ void k_zero(float* __restrict__ out) {
    int i = blockIdx.x * blockDim.x + threadIdx.x;
    int stride = gridDim.x * blockDim.x;
    float4 z = make_float4(0.f, 0.f, 0.f, 0.f);
    for (int j = i; j < Nc*Cc/4; j += stride) ((float4*)out)[j] = z;
    for (int j = i; j < Nc*Hc/4; j += stride) {
        ((float4*)g_q)[j] = z;
        ((float4*)g_k)[j] = z;
        ((float4*)g_v)[j] = z;
    }
    if (i < Ec) g_cnt[i] = 0;
}

// ---------------- prep: sim column norms + sigmoid(gates) ----------------
__global__ void k_prep(const float* __restrict__ sim, const float* __restrict__ gates) {
    int w = threadIdx.x >> 5, lane = threadIdx.x & 31;
    float s = 0.f;
    for (int i = lane; i < Cc; i += 32) {
        float v = sim[(size_t)i*Ec + w];
        s += v*v;
    }
    #pragma unroll
    for (int o = 16; o; o >>= 1) s += __shfl_xor_sync(0xffffffffu, s, o);
    if (lane == 0) g_wninv[w] = 1.0f / fmaxf(sqrtf(s), 1e-12f);
    if (threadIdx.x < Ec) g_sig[threadIdx.x] = 1.0f / (1.0f + expf(-gates[threadIdx.x]));
}

// ---------------- gating ----------------
__global__ void k_gate(const float* __restrict__ x, const float* __restrict__ sim) {
    int n0 = blockIdx.x * GT;
    float dot[GT][Ec];
    float ss[GT];
    #pragma unroll
    for (int j = 0; j < GT; j++) {
        ss[j] = 0.f;
        #pragma unroll
        for (int e = 0; e < Ec; e++) dot[j][e] = 0.f;
    }
    for (int i = threadIdx.x; i < Cc; i += 256) {
        float xv[GT];
        #pragma unroll
        for (int j = 0; j < GT; j++) {
            xv[j] = x[(size_t)(n0 + j)*Cc + i];
            ss[j] += xv[j]*xv[j];
        }
        const float4* s4 = (const float4*)(sim + (size_t)i*Ec);
        #pragma unroll
        for (int q = 0; q < 4; q++) {
            float4 sv = s4[q];
            #pragma unroll
            for (int j = 0; j < GT; j++) {
                dot[j][q*4+0] += xv[j]*sv.x;
                dot[j][q*4+1] += xv[j]*sv.y;
                dot[j][q*4+2] += xv[j]*sv.z;
                dot[j][q*4+3] += xv[j]*sv.w;
            }
        }
    }
    __shared__ float red[8][GT*Ec + GT];
    int wid = threadIdx.x >> 5, lane = threadIdx.x & 31;
    #pragma unroll
    for (int j = 0; j < GT; j++) {
        #pragma unroll
        for (int e = 0; e < Ec; e++) {
            float v = dot[j][e];
            #pragma unroll
            for (int o = 16; o; o >>= 1) v += __shfl_xor_sync(0xffffffffu, v, o);
            if (lane == 0) red[wid][j*Ec + e] = v;
        }
        float v = ss[j];
        #pragma unroll
        for (int o = 16; o; o >>= 1) v += __shfl_xor_sync(0xffffffffu, v, o);
        if (lane == 0) red[wid][GT*Ec + j] = v;
    }
    __syncthreads();
    if (threadIdx.x < GT*Ec + GT) {
        float s = 0.f;
        #pragma unroll
        for (int w = 0; w < 8; w++) s += red[w][threadIdx.x];
        red[0][threadIdx.x] = s;
    }
    __syncthreads();
    if (threadIdx.x < GT) {
        int j = threadIdx.x;
        int n = n0 + j;
        float xin = rsqrtf(fmaxf(red[0][GT*Ec + j], 1e-24f));
        float logitv[Ec], gatedv[Ec];
        int act = 0;
        #pragma unroll
        for (int e = 0; e < Ec; e++) {
            float lg = red[0][j*Ec + e] * xin * g_wninv[e] - g_sig[e];
            logitv[e] = lg;
            gatedv[e] = fmaxf(lg, 0.f);
            act += (lg > 0.f) ? 1 : 0;
        }
        unsigned mask = 0u;
        if (act > 0) {
            #pragma unroll
            for (int e = 0; e < Ec; e++) if (logitv[e] > 0.f) mask |= (1u << e);
        } else {
            int i1 = 0;
            #pragma unroll
            for (int e = 1; e < Ec; e++) if (logitv[e] > logitv[i1]) i1 = e;
            int i2 = (i1 == 0) ? 1 : 0;
            #pragma unroll
            for (int e = 0; e < Ec; e++)
                if (e != i1 && logitv[e] > logitv[i2]) i2 = e;
            mask = (1u << i1) | (1u << i2);
        }
        float m = -1e30f;
        #pragma unroll
        for (int e = 0; e < Ec; e++) if ((mask >> e) & 1u) m = fmaxf(m, gatedv[e]);
        float ssum = 0.f;
        float ex[Ec];
        #pragma unroll
        for (int e = 0; e < Ec; e++) {
            float t = ((mask >> e) & 1u) ? expf(gatedv[e] - m) : 0.f;
            ex[e] = t;
            ssum += t;
        }
        float sinv = 1.f / ssum;
        #pragma unroll
        for (int e = 0; e < Ec; e++) {
            if ((mask >> e) & 1u) {
                int p = atomicAdd(&g_cnt[e], 1);
                g_tok[e*Nc + p] = n;
                g_w[e*Nc + p]   = ex[e] * sinv;
            }
        }
    }
}

// ---------------- grouped GEMM: q/k/v = (w*x_gather) @ proj[e] ----------------
// Tile M=128 tokens x N=128, K-chunk 16, 8x8 per thread via FFMA2.
__global__ __launch_bounds__(256,2) void k_qkv(const float* __restrict__ x,
                                               const float* __restrict__ qp,
                                               const float* __restrict__ kp,
                                               const float* __restrict__ vp) {
    int e = blockIdx.y;
    int cnt = g_cnt[e];
    int m0 = blockIdx.x * 128;
    if (m0 >= cnt) return;
    const float* proj;
    float* dst;
    if (blockIdx.z == 0)      { proj = qp; dst = g_q; }
    else if (blockIdx.z == 1) { proj = kp; dst = g_k; }
    else                      { proj = vp; dst = g_v; }

    __shared__ float As[16][128];     // [k][m], A pre-scaled by routing weight
    __shared__ float Bs[16][128];     // [k][n]
    __shared__ int   sTok[128];
    __shared__ float sW[128];
    int tid = threadIdx.x;
    if (tid < 128) {
        int idx = m0 + tid;
        if (idx < cnt) { sTok[tid] = g_tok[e*Nc + idx]; sW[tid] = g_w[e*Nc + idx]; }
        else           { sTok[tid] = -1;                 sW[tid] = 0.f; }
    }
    __syncthreads();

    int ty = tid >> 4, tx = tid & 15;
    // A loader role: row am, k-half ak
    int am = tid & 127, ak = (tid >> 7) * 8;
    int atok = sTok[am];
    float aw = sW[am];
    const float* asrc = x + (size_t)(atok < 0 ? 0 : atok)*Cc + ak;
    // B loader role
    int bk = tid >> 4, bc = (tid & 15) * 8;
    const float* bsrc = proj + ((size_t)e*Cc + bk)*Hc + bc;

    float4 z4 = make_float4(0.f,0.f,0.f,0.f);
    float4 ra0 = z4, ra1 = z4, rb0, rb1;
    if (atok >= 0) { ra0 = *(const float4*)(asrc); ra1 = *(const float4*)(asrc + 4); }
    rb0 = *(const float4*)(bsrc); rb1 = *(const float4*)(bsrc + 4);

    unsigned long long acc[4][8];
    #pragma unroll
    for (int p = 0; p < 4; p++)
        #pragma unroll
        for (int j = 0; j < 8; j++) acc[p][j] = 0ull;

    const int NCH = Cc / 16;
    for (int c = 0; c < NCH; c++) {
        __syncthreads();
        As[ak+0][am] = ra0.x*aw; As[ak+1][am] = ra0.y*aw;
        As[ak+2][am] = ra0.z*aw; As[ak+3][am] = ra0.w*aw;
        As[ak+4][am] = ra1.x*aw; As[ak+5][am] = ra1.y*aw;
        As[ak+6][am] = ra1.z*aw; As[ak+7][am] = ra1.w*aw;
        *(float4*)&Bs[bk][bc]     = rb0;
        *(float4*)&Bs[bk][bc + 4] = rb1;
        __syncthreads();
        if (c + 1 < NCH) {
            if (atok >= 0) {
                ra0 = *(const float4*)(asrc + (c+1)*16);
                ra1 = *(const float4*)(asrc + (c+1)*16 + 4);
            }
            rb0 = *(const float4*)(bsrc + (size_t)(c+1)*16*Hc);
            rb1 = *(const float4*)(bsrc + (size_t)(c+1)*16*Hc + 4);
        }
        #pragma unroll
        for (int kk = 0; kk < 16; kk++) {
            ulonglong2 a01 = *(ulonglong2*)&As[kk][ty*8];      // rows (0,1),(2,3)
            ulonglong2 a23 = *(ulonglong2*)&As[kk][ty*8 + 4];  // rows (4,5),(6,7)
            float4 b0 = *(float4*)&Bs[kk][tx*8];
            float4 b1 = *(float4*)&Bs[kk][tx*8 + 4];
            unsigned long long bb[8];
            bb[0] = pack2(b0.x, b0.x); bb[1] = pack2(b0.y, b0.y);
            bb[2] = pack2(b0.z, b0.z); bb[3] = pack2(b0.w, b0.w);
            bb[4] = pack2(b1.x, b1.x); bb[5] = pack2(b1.y, b1.y);
            bb[6] = pack2(b1.z, b1.z); bb[7] = pack2(b1.w, b1.w);
            #pragma unroll
            for (int j = 0; j < 8; j++) {
                ffma2(acc[0][j], a01.x, bb[j]);
                ffma2(acc[1][j], a01.y, bb[j]);
                ffma2(acc[2][j], a23.x, bb[j]);
                ffma2(acc[3][j], a23.y, bb[j]);
            }
        }
    }
    #pragma unroll
    for (int p = 0; p < 4; p++) {
        int r0 = ty*8 + 2*p;
        int tok0 = sTok[r0], tok1 = sTok[r0 + 1];
        #pragma unroll
        for (int j = 0; j < 8; j++) {
            float lo, hi;
            unpack2(acc[p][j], lo, hi);
            if (tok0 >= 0) atomicAdd(dst + (size_t)tok0*Hc + tx*8 + j, lo);
            if (tok1 >= 0) atomicAdd(dst + (size_t)tok1*Hc + tx*8 + j, hi);
        }
    }
}

// ---------------- RoPE in-place on g_q, g_k ----------------
__global__ void k_rope(const int* __restrict__ pid) {
    int idx = blockIdx.x * blockDim.x + threadIdx.x;
    if (idx >= Nc*64) return;
    int n = idx >> 6;
    int i = idx & 63;
    int t = pid[n & (Tc - 1)];
    float ang = (float)t * exp2f(-(float)i * (13.28771237954945f / 64.0f));
    float s, c;
    sincosf(ang, &s, &c);
    size_t base = (size_t)n * Hc;
    float q0 = g_q[base + i], q1 = g_q[base + i + 64];
    g_q[base + i]      = q0*c - q1*s;
    g_q[base + i + 64] = q1*c + q0*s;
    float k0 = g_k[base + i], k1 = g_k[base + i + 64];
    g_k[base + i]      = k0*c - k1*s;
    g_k[base + i + 64] = k1*c + k0*s;
}

// ---------------- causal flash attention (single head, fp32) ----------------
__global__ __launch_bounds__(256) void k_attn() {
    int qt = blockIdx.x, b = blockIdx.y;
    int q0 = qt * 32;
    __shared__ float Qs[32][128];
    __shared__ float KVs[32][128];
    __shared__ float Ps[32][32];
    __shared__ float sM[32], sL[32];
    int tid = threadIdx.x;
    int row = tid >> 3;
    int cg  = tid & 7;

    {
        const float* src = g_q + ((size_t)(b*Tc + q0 + row))*Hc + cg*16;
        #pragma unroll
        for (int j = 0; j < 4; j++)
            *(float4*)&Qs[row][cg*16 + 4*j] = *(const float4*)(src + 4*j);
    }
    if (tid < 32) { sM[tid] = -1e30f; sL[tid] = 0.f; }

    float accO[16];
    #pragma unroll
    for (int j = 0; j < 16; j++) accO[j] = 0.f;
    const float scale = 0.08838834764831845f;

    for (int kt = 0; kt <= qt; kt++) {
        int k0 = kt * 32;
        {
            const float* src = g_k + ((size_t)(b*Tc + k0 + row))*Hc + cg*16;
            #pragma unroll
            for (int j = 0; j < 4; j++)
                *(float4*)&KVs[row][cg*16 + 4*j] = *(const float4*)(src + 4*j);
        }
        __syncthreads();

        float s4a[4] = {0.f, 0.f, 0.f, 0.f};
        int cb = cg * 4;
        #pragma unroll 8
        for (int k4 = 0; k4 < 32; k4++) {
            float4 q4 = *(float4*)&Qs[row][k4*4];
            #pragma unroll
            for (int c = 0; c < 4; c++) {
                float4 kv = *(float4*)&KVs[cb + c][k4*4];
                s4a[c] += q4.x*kv.x + q4.y*kv.y + q4.z*kv.z + q4.w*kv.w;
            }
        }
        float sv[4];
        float mloc = -1e30f;
        #pragma unroll
        for (int c = 0; c < 4; c++) {
            int kpos = k0 + cb + c;
            sv[c] = (kpos <= q0 + row) ? s4a[c]*scale : -1e30f;
            mloc = fmaxf(mloc, sv[c]);
        }
        #pragma unroll
        for (int o = 1; o < 8; o <<= 1) mloc = fmaxf(mloc, __shfl_xor_sync(0xffffffffu, mloc, o));
        float mprev = sM[row];
        float mnew = fmaxf(mprev, mloc);
        float p[4];
        float ps = 0.f;
        #pragma unroll
        for (int c = 0; c < 4; c++) { p[c] = __expf(sv[c] - mnew); ps += p[c]; }
        #pragma unroll
        for (int o = 1; o < 8; o <<= 1) ps += __shfl_xor_sync(0xffffffffu, ps, o);
        float alpha = __expf(mprev - mnew);
        #pragma unroll
        for (int j = 0; j < 16; j++) accO[j] *= alpha;
        if (cg == 0) { sM[row] = mnew; sL[row] = sL[row]*alpha + ps; }
        #pragma unroll
        for (int c = 0; c < 4; c++) Ps[row][cb + c] = p[c];
        __syncthreads();
        {
            const float* src = g_v + ((size_t)(b*Tc + k0 + row))*Hc + cg*16;
            #pragma unroll
            for (int j = 0; j < 4; j++)
                *(float4*)&KVs[row][cg*16 + 4*j] = *(const float4*)(src + 4*j);
        }
        __syncthreads();
        #pragma unroll 4
        for (int kp = 0; kp < 32; kp++) {
            float pv = Ps[row][kp];
            #pragma unroll
            for (int j4 = 0; j4 < 4; j4++) {
                float4 v4 = *(float4*)&KVs[kp][cg*16 + 4*j4];
                accO[j4*4+0] += pv*v4.x; accO[j4*4+1] += pv*v4.y;
                accO[j4*4+2] += pv*v4.z; accO[j4*4+3] += pv*v4.w;
            }
        }
        __syncthreads();
    }
    float linv = 1.0f / sL[row];
    float* dst = g_attn + ((size_t)(b*Tc + q0 + row))*Hc + cg*16;
    #pragma unroll
    for (int j = 0; j < 16; j++) dst[j] = accO[j]*linv;
}

// ---------------- grouped GEMM: out += (w*attn_gather) @ o_proj[e] ----------------
// Tile M=128 tokens x N=128 out cols (z), K=128 in chunks of 16.
__global__ __launch_bounds__(256,2) void k_oproj(const float* __restrict__ op,
                                                 float* __restrict__ out) {
    int e = blockIdx.y;
    int cnt = g_cnt[e];
    int m0 = blockIdx.x * 128;
    if (m0 >= cnt) return;
    int z = blockIdx.z;

    __shared__ float As[16][128];
    __shared__ float Bs[16][128];
    __shared__ int   sTok[128];
    __shared__ float sW[128];
    int tid = threadIdx.x;
    if (tid < 128) {
        int idx = m0 + tid;
        if (idx < cnt) { sTok[tid] = g_tok[e*Nc + idx]; sW[tid] = g_w[e*Nc + idx]; }
        else           { sTok[tid] = -1;                 sW[tid] = 0.f; }
    }
    __syncthreads();

    int ty = tid >> 4, tx = tid & 15;
    int am = tid & 127, ak = (tid >> 7) * 8;
    int atok = sTok[am];
    float aw = sW[am];
    const float* asrc = g_attn + (size_t)(atok < 0 ? 0 : atok)*Hc + ak;
    int bk = tid >> 4, bc = (tid & 15) * 8;
    const float* bsrc = op + ((size_t)e*Hc + bk)*Cc + z*128 + bc;

    float4 z4 = make_float4(0.f,0.f,0.f,0.f);
    float4 ra0 = z4, ra1 = z4, rb0, rb1;
    if (atok >= 0) { ra0 = *(const float4*)(asrc); ra1 = *(const float4*)(asrc + 4); }
    rb0 = *(const float4*)(bsrc); rb1 = *(const float4*)(bsrc + 4);

    unsigned long long acc[4][8];
    #pragma unroll
    for (int p = 0; p < 4; p++)
        #pragma unroll
        for (int j = 0; j < 8; j++) acc[p][j] = 0ull;

    const int NCH = Hc / 16;
    for (int c = 0; c < NCH; c++) {
        __syncthreads();
        As[ak+0][am] = ra0.x*aw; As[ak+1][am] = ra0.y*aw;
        As[ak+2][am] = ra0.z*aw; As[ak+3][am] = ra0.w*aw;
        As[ak+4][am] = ra1.x*aw; As[ak+5][am] = ra1.y*aw;
        As[ak+6][am] = ra1.z*aw; As[ak+7][am] = ra1.w*aw;
        *(float4*)&Bs[bk][bc]     = rb0;
        *(float4*)&Bs[bk][bc + 4] = rb1;
        __syncthreads();
        if (c + 1 < NCH) {
            if (atok >= 0) {
                ra0 = *(const float4*)(asrc + (c+1)*16);
                ra1 = *(const float4*)(asrc + (c+1)*16 + 4);
            }
            rb0 = *(const float4*)(bsrc + (size_t)(c+1)*16*Cc);
            rb1 = *(const float4*)(bsrc + (size_t)(c+1)*16*Cc + 4);
        }
        #pragma unroll
        for (int kk = 0; kk < 16; kk++) {
            ulonglong2 a01 = *(ulonglong2*)&As[kk][ty*8];
            ulonglong2 a23 = *(ulonglong2*)&As[kk][ty*8 + 4];
            float4 b0 = *(float4*)&Bs[kk][tx*8];
            float4 b1 = *(float4*)&Bs[kk][tx*8 + 4];
            unsigned long long bb[8];
            bb[0] = pack2(b0.x, b0.x); bb[1] = pack2(b0.y, b0.y);
            bb[2] = pack2(b0.z, b0.z); bb[3] = pack2(b0.w, b0.w);
            bb[4] = pack2(b1.x, b1.x); bb[5] = pack2(b1.y, b1.y);
            bb[6] = pack2(b1.z, b1.z); bb[7] = pack2(b1.w, b1.w);
            #pragma unroll
            for (int j = 0; j < 8; j++) {
                ffma2(acc[0][j], a01.x, bb[j]);
                ffma2(acc[1][j], a01.y, bb[j]);
                ffma2(acc[2][j], a23.x, bb[j]);
                ffma2(acc[3][j], a23.y, bb[j]);
            }
        }
    }
    #pragma unroll
    for (int p = 0; p < 4; p++) {
        int r0 = ty*8 + 2*p;
        int tok0 = sTok[r0], tok1 = sTok[r0 + 1];
        #pragma unroll
        for (int j = 0; j < 8; j++) {
            float lo, hi;
            unpack2(acc[p][j], lo, hi);
            if (tok0 >= 0) atomicAdd(out + (size_t)tok0*Cc + z*128 + tx*8 + j, lo);
            if (tok1 >= 0) atomicAdd(out + (size_t)tok1*Cc + z*128 + tx*8 + j, hi);
        }
    }
}

// ---------------- launch ----------------
extern "C" void kernel_launch(void* const* d_in, const int* in_sizes, int n_in,
                              void* d_out, int out_size) {
    const float* x     = (const float*)d_in[0];
    const int*   pid   = (const int*)  d_in[1];
    const float* sim   = (const float*)d_in[2];
    const float* gates = (const float*)d_in[3];
    const float* qp    = (const float*)d_in[4];
    const float* kp    = (const float*)d_in[5];
    const float* vp    = (const float*)d_in[6];
    const float* op    = (const float*)d_in[7];
    float* out = (float*)d_out;

    k_zero <<<4096, 256>>>(out);
    k_prep <<<1, 512>>>(sim, gates);
    k_gate <<<Nc/GT, 256>>>(x, sim);
    k_qkv  <<<dim3(Nc/128, Ec, 3), 256>>>(x, qp, kp, vp);
    k_rope <<<(Nc*64)/256, 256>>>(pid);
    k_attn <<<dim3(Tc/32, Bc), 256>>>();
    k_oproj<<<dim3(Nc/128, Ec, 16), 256>>>(op, out);
}

// round 4
// speedup vs baseline: 1.4448x; 1.3004x over previous
#include <cuda_runtime.h>
#include <cuda_bf16.h>
#include <math.h>
#include <stdint.h>

#define Bc 4
#define Tc 2048
#define Cc 2048
#define Hc 128
#define Ec 16
#define Nc (Bc*Tc)
#define GT 4

// ---------------- device scratch (no allocations allowed) ----------------
__device__ float g_q[Nc*Hc];
__device__ float g_k[Nc*Hc];
__device__ float g_v[Nc*Hc];
__device__ int   g_cnt[Ec];
__device__ int   g_tok[Ec*Nc];
__device__ float g_w[Ec*Nc];
__device__ float g_wninv[Ec];
__device__ float g_sig[Ec];

// bf16 split operands
__device__ __nv_bfloat16 xhi[(size_t)Nc*Cc], xlo[(size_t)Nc*Cc];
__device__ __nv_bfloat16 pqh[(size_t)Ec*Hc*Cc], pql[(size_t)Ec*Hc*Cc];
__device__ __nv_bfloat16 pkh[(size_t)Ec*Hc*Cc], pkl[(size_t)Ec*Hc*Cc];
__device__ __nv_bfloat16 pvh[(size_t)Ec*Hc*Cc], pvl[(size_t)Ec*Hc*Cc];
__device__ __nv_bfloat16 poh[(size_t)Ec*Cc*Hc], pol[(size_t)Ec*Cc*Hc];
__device__ __nv_bfloat16 g_ahi[Nc*Hc], g_alo[Nc*Hc];

// ---------------- helpers ----------------
__device__ __forceinline__ uint32_t smem_u32(const void* p) {
    uint32_t a;
    asm("{ .reg .u64 t; cvta.to.shared.u64 t, %1; cvt.u32.u64 %0, t; }" : "=r"(a) : "l"(p));
    return a;
}
__device__ __forceinline__ void ldm4(uint32_t* r, uint32_t a) {
    asm volatile("ldmatrix.sync.aligned.m8n8.x4.shared.b16 {%0,%1,%2,%3}, [%4];"
        : "=r"(r[0]), "=r"(r[1]), "=r"(r[2]), "=r"(r[3]) : "r"(a));
}
__device__ __forceinline__ void mma16816(float* d, const uint32_t* a, const uint32_t* b) {
    asm volatile("mma.sync.aligned.m16n8k16.row.col.f32.bf16.bf16.f32 "
        "{%0,%1,%2,%3},{%4,%5,%6,%7},{%8,%9},{%0,%1,%2,%3};"
        : "+f"(d[0]), "+f"(d[1]), "+f"(d[2]), "+f"(d[3])
        : "r"(a[0]), "r"(a[1]), "r"(a[2]), "r"(a[3]), "r"(b[0]), "r"(b[1]));
}
__device__ __forceinline__ void cpa(uint32_t dst, const void* src, int zf) {
    asm volatile("cp.async.cg.shared.global [%0], [%1], 16, %2;"
        :: "r"(dst), "l"((unsigned long long)__cvta_generic_to_global(src)), "r"(zf) : "memory");
}
__device__ __forceinline__ void red2(float* p, float x, float y) {
    asm volatile("red.global.add.v2.f32 [%0], {%1,%2};"
        :: "l"((unsigned long long)__cvta_generic_to_global(p)), "f"(x), "f"(y) : "memory");
}
#define CP_COMMIT asm volatile("cp.async.commit_group;" ::: "memory")

// ---------------- zero scratch + output ----------------
__global__ void k_zero(float* __restrict__ out) {
    int i = blockIdx.x * blockDim.x + threadIdx.x;
    int stride = gridDim.x * blockDim.x;
    float4 z = make_float4(0.f, 0.f, 0.f, 0.f);
    for (int j = i; j < Nc*Cc/4; j += stride) ((float4*)out)[j] = z;
    for (int j = i; j < Nc*Hc/4; j += stride) {
        ((float4*)g_q)[j] = z;
        ((float4*)g_k)[j] = z;
        ((float4*)g_v)[j] = z;
    }
    if (i < Ec) g_cnt[i] = 0;
}

// ---------------- prep ----------------
__global__ void k_prep(const float* __restrict__ sim, const float* __restrict__ gates) {
    int w = threadIdx.x >> 5, lane = threadIdx.x & 31;
    float s = 0.f;
    for (int i = lane; i < Cc; i += 32) {
        float v = sim[(size_t)i*Ec + w];
        s += v*v;
    }
    #pragma unroll
    for (int o = 16; o; o >>= 1) s += __shfl_xor_sync(0xffffffffu, s, o);
    if (lane == 0) g_wninv[w] = 1.0f / fmaxf(sqrtf(s), 1e-12f);
    if (threadIdx.x < Ec) g_sig[threadIdx.x] = 1.0f / (1.0f + expf(-gates[threadIdx.x]));
}

// ---------------- gating ----------------
__global__ void k_gate(const float* __restrict__ x, const float* __restrict__ sim) {
    int n0 = blockIdx.x * GT;
    float dot[GT][Ec];
    float ss[GT];
    #pragma unroll
    for (int j = 0; j < GT; j++) {
        ss[j] = 0.f;
        #pragma unroll
        for (int e = 0; e < Ec; e++) dot[j][e] = 0.f;
    }
    for (int i = threadIdx.x; i < Cc; i += 256) {
        float xv[GT];
        #pragma unroll
        for (int j = 0; j < GT; j++) {
            xv[j] = x[(size_t)(n0 + j)*Cc + i];
            ss[j] += xv[j]*xv[j];
        }
        const float4* s4 = (const float4*)(sim + (size_t)i*Ec);
        #pragma unroll
        for (int q = 0; q < 4; q++) {
            float4 sv = s4[q];
            #pragma unroll
            for (int j = 0; j < GT; j++) {
                dot[j][q*4+0] += xv[j]*sv.x;
                dot[j][q*4+1] += xv[j]*sv.y;
                dot[j][q*4+2] += xv[j]*sv.z;
                dot[j][q*4+3] += xv[j]*sv.w;
            }
        }
    }
    __shared__ float red[8][GT*Ec + GT];
    int wid = threadIdx.x >> 5, lane = threadIdx.x & 31;
    #pragma unroll
    for (int j = 0; j < GT; j++) {
        #pragma unroll
        for (int e = 0; e < Ec; e++) {
            float v = dot[j][e];
            #pragma unroll
            for (int o = 16; o; o >>= 1) v += __shfl_xor_sync(0xffffffffu, v, o);
            if (lane == 0) red[wid][j*Ec + e] = v;
        }
        float v = ss[j];
        #pragma unroll
        for (int o = 16; o; o >>= 1) v += __shfl_xor_sync(0xffffffffu, v, o);
        if (lane == 0) red[wid][GT*Ec + j] = v;
    }
    __syncthreads();
    if (threadIdx.x < GT*Ec + GT) {
        float s = 0.f;
        #pragma unroll
        for (int w = 0; w < 8; w++) s += red[w][threadIdx.x];
        red[0][threadIdx.x] = s;
    }
    __syncthreads();
    if (threadIdx.x < GT) {
        int j = threadIdx.x;
        int n = n0 + j;
        float xin = rsqrtf(fmaxf(red[0][GT*Ec + j], 1e-24f));
        float logitv[Ec], gatedv[Ec];
        int act = 0;
        #pragma unroll
        for (int e = 0; e < Ec; e++) {
            float lg = red[0][j*Ec + e] * xin * g_wninv[e] - g_sig[e];
            logitv[e] = lg;
            gatedv[e] = fmaxf(lg, 0.f);
            act += (lg > 0.f) ? 1 : 0;
        }
        unsigned mask = 0u;
        if (act > 0) {
            #pragma unroll
            for (int e = 0; e < Ec; e++) if (logitv[e] > 0.f) mask |= (1u << e);
        } else {
            int i1 = 0;
            #pragma unroll
            for (int e = 1; e < Ec; e++) if (logitv[e] > logitv[i1]) i1 = e;
            int i2 = (i1 == 0) ? 1 : 0;
            #pragma unroll
            for (int e = 0; e < Ec; e++)
                if (e != i1 && logitv[e] > logitv[i2]) i2 = e;
            mask = (1u << i1) | (1u << i2);
        }
        float m = -1e30f;
        #pragma unroll
        for (int e = 0; e < Ec; e++) if ((mask >> e) & 1u) m = fmaxf(m, gatedv[e]);
        float ssum = 0.f;
        float ex[Ec];
        #pragma unroll
        for (int e = 0; e < Ec; e++) {
            float t = ((mask >> e) & 1u) ? expf(gatedv[e] - m) : 0.f;
            ex[e] = t;
            ssum += t;
        }
        float sinv = 1.f / ssum;
        #pragma unroll
        for (int e = 0; e < Ec; e++) {
            if ((mask >> e) & 1u) {
                int p = atomicAdd(&g_cnt[e], 1);
                g_tok[e*Nc + p] = n;
                g_w[e*Nc + p]   = ex[e] * sinv;
            }
        }
    }
}

// ---------------- conversions ----------------
__global__ void k_convx(const float* __restrict__ x) {
    int i = blockIdx.x * blockDim.x + threadIdx.x;
    float4 v = ((const float4*)x)[i];
    __nv_bfloat16 h0 = __float2bfloat16_rn(v.x), h1 = __float2bfloat16_rn(v.y);
    __nv_bfloat16 h2 = __float2bfloat16_rn(v.z), h3 = __float2bfloat16_rn(v.w);
    __nv_bfloat16 l0 = __float2bfloat16_rn(v.x - __bfloat162float(h0));
    __nv_bfloat16 l1 = __float2bfloat16_rn(v.y - __bfloat162float(h1));
    __nv_bfloat16 l2 = __float2bfloat16_rn(v.z - __bfloat162float(h2));
    __nv_bfloat16 l3 = __float2bfloat16_rn(v.w - __bfloat162float(h3));
    ((__nv_bfloat162*)xhi)[i*2]   = __nv_bfloat162(h0, h1);
    ((__nv_bfloat162*)xhi)[i*2+1] = __nv_bfloat162(h2, h3);
    ((__nv_bfloat162*)xlo)[i*2]   = __nv_bfloat162(l0, l1);
    ((__nv_bfloat162*)xlo)[i*2+1] = __nv_bfloat162(l2, l3);
}

__global__ void k_convp(const float* __restrict__ qp, const float* __restrict__ kp,
                        const float* __restrict__ vp) {
    const float* src = (blockIdx.z == 0) ? qp : (blockIdx.z == 1) ? kp : vp;
    __nv_bfloat16* dh = (blockIdx.z == 0) ? pqh : (blockIdx.z == 1) ? pkh : pvh;
    __nv_bfloat16* dl = (blockIdx.z == 0) ? pql : (blockIdx.z == 1) ? pkl : pvl;
    int e = blockIdx.y;
    int c0 = (blockIdx.x >> 2) * 32, h0 = (blockIdx.x & 3) * 32;
    __shared__ float tile[32][33];
    int tx = threadIdx.x & 31, ty = threadIdx.x >> 5;
    #pragma unroll
    for (int cy = 0; cy < 32; cy += 8)
        tile[ty + cy][tx] = src[((size_t)e*Cc + c0 + ty + cy)*Hc + h0 + tx];
    __syncthreads();
    #pragma unroll
    for (int hy = 0; hy < 32; hy += 8) {
        float v = tile[tx][ty + hy];
        size_t o = ((size_t)e*Hc + h0 + ty + hy)*Cc + c0 + tx;
        __nv_bfloat16 hh = __float2bfloat16_rn(v);
        dh[o] = hh;
        dl[o] = __float2bfloat16_rn(v - __bfloat162float(hh));
    }
}

__global__ void k_convo(const float* __restrict__ op) {
    int e = blockIdx.y;
    int c0 = (blockIdx.x >> 2) * 32, h0 = (blockIdx.x & 3) * 32;
    __shared__ float tile[32][33];
    int tx = threadIdx.x & 31, ty = threadIdx.x >> 5;
    #pragma unroll
    for (int hy = 0; hy < 32; hy += 8)
        tile[ty + hy][tx] = op[((size_t)e*Hc + h0 + ty + hy)*Cc + c0 + tx];
    __syncthreads();
    #pragma unroll
    for (int cy = 0; cy < 32; cy += 8) {
        float v = tile[tx][ty + cy];
        size_t o = ((size_t)e*Cc + c0 + ty + cy)*Hc + h0 + tx;
        __nv_bfloat16 hh = __float2bfloat16_rn(v);
        poh[o] = hh;
        pol[o] = __float2bfloat16_rn(v - __bfloat162float(hh));
    }
}

// ---------------- warp-MMA grouped QKV GEMM ----------------
// Tile M=128 tokens x N=128(H), K=2048 in 32 stages of 64.
// smem: [0:512) sTok, [512:1024) sW, [1024:) 2 stage buffers of 64KB:
//   within buffer: Ahi(16K) Alo(16K) Bhi(16K) Blo(16K); tile rows = 128B, XOR-swizzled.
__global__ __launch_bounds__(256, 1) void k_qkv_mma() {
    extern __shared__ char smem[];
    int e = blockIdx.y;
    int cnt = g_cnt[e];
    int m0 = blockIdx.x * 128;
    if (m0 >= cnt) return;
    const __nv_bfloat16 *BH, *BL;
    float* dst;
    if (blockIdx.z == 0)      { BH = pqh; BL = pql; dst = g_q; }
    else if (blockIdx.z == 1) { BH = pkh; BL = pkl; dst = g_k; }
    else                      { BH = pvh; BL = pvl; dst = g_v; }

    int* sTok = (int*)smem;
    float* sW = (float*)(smem + 512);
    uint32_t tiles = smem_u32(smem) + 1024;
    int tid = threadIdx.x;

    if (tid < 128) {
        int i = m0 + tid;
        if (i < cnt) { sTok[tid] = g_tok[e*Nc + i]; sW[tid] = g_w[e*Nc + i]; }
        else         { sTok[tid] = -1;               sW[tid] = 0.f; }
    }
    __syncthreads();

    // loader: thread t -> row t/2, chunks (t&1)*4 .. +3 of each array
    int lrow = tid >> 1;
    int lc0 = (tid & 1) * 4;
    int ltok = sTok[lrow];
    int zf = (ltok >= 0) ? 16 : 0;
    const __nv_bfloat16* aH = xhi + (size_t)(ltok < 0 ? 0 : ltok)*Cc;
    const __nv_bfloat16* aL = xlo + (size_t)(ltok < 0 ? 0 : ltok)*Cc;
    const __nv_bfloat16* bH = BH + ((size_t)e*Hc + lrow)*Cc;
    const __nv_bfloat16* bL = BL + ((size_t)e*Hc + lrow)*Cc;
    uint32_t loff[4];
    #pragma unroll
    for (int u = 0; u < 4; u++) {
        int c = lc0 + u;
        loff[u] = lrow*128 + ((c ^ (lrow & 7)) << 4);
    }
    auto loadStage = [&](int s) {
        uint32_t base = tiles + (s & 1) * 65536;
        int k0 = s * 64;
        #pragma unroll
        for (int u = 0; u < 4; u++) {
            int c = lc0 + u;
            uint32_t d0 = base + loff[u];
            cpa(d0,         aH + k0 + c*8, zf);
            cpa(d0 + 16384, aL + k0 + c*8, zf);
            cpa(d0 + 32768, bH + k0 + c*8, 16);
            cpa(d0 + 49152, bL + k0 + c*8, 16);
        }
        CP_COMMIT;
    };

    int w = tid >> 5, lane = tid & 31;
    int wr = w & 3, wc = w >> 2;
    int aRow  = wr*32 + (lane & 15);
    int aCB   = lane >> 4;
    int bRowB = wc*64 + (lane & 7) + ((lane >> 4) << 3);
    int bCB   = (lane >> 3) & 1;

    float d[2][8][4];
    #pragma unroll
    for (int mt = 0; mt < 2; mt++)
        #pragma unroll
        for (int nt = 0; nt < 8; nt++)
            #pragma unroll
            for (int q = 0; q < 4; q++) d[mt][nt][q] = 0.f;

    loadStage(0);
    for (int s = 0; s < 32; s++) {
        if (s < 31) {
            loadStage(s + 1);
            asm volatile("cp.async.wait_group 1;" ::: "memory");
        } else {
            asm volatile("cp.async.wait_group 0;" ::: "memory");
        }
        __syncthreads();
        uint32_t base = tiles + (s & 1) * 65536;
        #pragma unroll
        for (int kc = 0; kc < 4; kc++) {
            uint32_t ah[2][4], al[2][4];
            #pragma unroll
            for (int mt = 0; mt < 2; mt++) {
                int r = aRow + mt*16;
                uint32_t ad = base + r*128 + ((((kc << 1) + aCB) ^ (r & 7)) << 4);
                ldm4(ah[mt], ad);
                ldm4(al[mt], ad + 16384);
            }
            #pragma unroll
            for (int np = 0; np < 4; np++) {
                int r = bRowB + np*16;
                uint32_t bd = base + 32768 + r*128 + ((((kc << 1) + bCB) ^ (r & 7)) << 4);
                uint32_t bh[4], bl[4];
                ldm4(bh, bd);
                ldm4(bl, bd + 16384);
                #pragma unroll
                for (int mt = 0; mt < 2; mt++) {
                    #pragma unroll
                    for (int i = 0; i < 2; i++) {
                        float* acc = d[mt][np*2 + i];
                        mma16816(acc, ah[mt], bh + 2*i);
                        mma16816(acc, ah[mt], bl + 2*i);
                        mma16816(acc, al[mt], bh + 2*i);
                    }
                }
            }
        }
        __syncthreads();
    }

    #pragma unroll
    for (int mt = 0; mt < 2; mt++) {
        int r0 = wr*32 + mt*16 + (lane >> 2);
        int r1 = r0 + 8;
        int t0 = sTok[r0], t1 = sTok[r1];
        float w0 = sW[r0], w1 = sW[r1];
        #pragma unroll
        for (int nt = 0; nt < 8; nt++) {
            int col = wc*64 + nt*8 + (lane & 3)*2;
            if (t0 >= 0) red2(dst + (size_t)t0*Hc + col, d[mt][nt][0]*w0, d[mt][nt][1]*w0);
            if (t1 >= 0) red2(dst + (size_t)t1*Hc + col, d[mt][nt][2]*w1, d[mt][nt][3]*w1);
        }
    }
}

// ---------------- RoPE ----------------
__global__ void k_rope(const int* __restrict__ pid) {
    int idx = blockIdx.x * blockDim.x + threadIdx.x;
    if (idx >= Nc*64) return;
    int n = idx >> 6;
    int i = idx & 63;
    int t = pid[n & (Tc - 1)];
    float ang = (float)t * exp2f(-(float)i * (13.28771237954945f / 64.0f));
    float s, c;
    sincosf(ang, &s, &c);
    size_t base = (size_t)n * Hc;
    float q0 = g_q[base + i], q1 = g_q[base + i + 64];
    g_q[base + i]      = q0*c - q1*s;
    g_q[base + i + 64] = q1*c + q0*s;
    float k0 = g_k[base + i], k1 = g_k[base + i + 64];
    g_k[base + i]      = k0*c - k1*s;
    g_k[base + i + 64] = k1*c + k0*s;
}

// ---------------- causal flash attention (fp32) ----------------
__global__ __launch_bounds__(256) void k_attn() {
    int qt = gridDim.x - 1 - blockIdx.x;
    int b = blockIdx.y;
    int q0 = qt * 32;
    __shared__ float Qs[32][128];
    __shared__ float KVs[32][128];
    __shared__ float Ps[32][32];
    __shared__ float sM[32], sL[32];
    int tid = threadIdx.x;
    int row = tid >> 3;
    int cg  = tid & 7;

    {
        const float* src = g_q + ((size_t)(b*Tc + q0 + row))*Hc + cg*16;
        #pragma unroll
        for (int j = 0; j < 4; j++)
            *(float4*)&Qs[row][cg*16 + 4*j] = *(const float4*)(src + 4*j);
    }
    if (tid < 32) { sM[tid] = -1e30f; sL[tid] = 0.f; }

    float accO[16];
    #pragma unroll
    for (int j = 0; j < 16; j++) accO[j] = 0.f;
    const float scale = 0.08838834764831845f;

    for (int kt = 0; kt <= qt; kt++) {
        int k0 = kt * 32;
        {
            const float* src = g_k + ((size_t)(b*Tc + k0 + row))*Hc + cg*16;
            #pragma unroll
            for (int j = 0; j < 4; j++)
                *(float4*)&KVs[row][cg*16 + 4*j] = *(const float4*)(src + 4*j);
        }
        __syncthreads();

        float s4a[4] = {0.f, 0.f, 0.f, 0.f};
        int cb = cg * 4;
        #pragma unroll 8
        for (int k4 = 0; k4 < 32; k4++) {
            float4 q4 = *(float4*)&Qs[row][k4*4];
            #pragma unroll
            for (int c = 0; c < 4; c++) {
                float4 kv = *(float4*)&KVs[cb + c][k4*4];
                s4a[c] += q4.x*kv.x + q4.y*kv.y + q4.z*kv.z + q4.w*kv.w;
            }
        }
        float sv[4];
        float mloc = -1e30f;
        #pragma unroll
        for (int c = 0; c < 4; c++) {
            int kpos = k0 + cb + c;
            sv[c] = (kpos <= q0 + row) ? s4a[c]*scale : -1e30f;
            mloc = fmaxf(mloc, sv[c]);
        }
        #pragma unroll
        for (int o = 1; o < 8; o <<= 1) mloc = fmaxf(mloc, __shfl_xor_sync(0xffffffffu, mloc, o));
        float mprev = sM[row];
        float mnew = fmaxf(mprev, mloc);
        float p[4];
        float ps = 0.f;
        #pragma unroll
        for (int c = 0; c < 4; c++) { p[c] = __expf(sv[c] - mnew); ps += p[c]; }
        #pragma unroll
        for (int o = 1; o < 8; o <<= 1) ps += __shfl_xor_sync(0xffffffffu, ps, o);
        float alpha = __expf(mprev - mnew);
        #pragma unroll
        for (int j = 0; j < 16; j++) accO[j] *= alpha;
        if (cg == 0) { sM[row] = mnew; sL[row] = sL[row]*alpha + ps; }
        #pragma unroll
        for (int c = 0; c < 4; c++) Ps[row][cb + c] = p[c];
        __syncthreads();
        {
            const float* src = g_v + ((size_t)(b*Tc + k0 + row))*Hc + cg*16;
            #pragma unroll
            for (int j = 0; j < 4; j++)
                *(float4*)&KVs[row][cg*16 + 4*j] = *(const float4*)(src + 4*j);
        }
        __syncthreads();
        #pragma unroll 4
        for (int kp = 0; kp < 32; kp++) {
            float pv = Ps[row][kp];
            #pragma unroll
            for (int j4 = 0; j4 < 4; j4++) {
                float4 v4 = *(float4*)&KVs[kp][cg*16 + 4*j4];
                accO[j4*4+0] += pv*v4.x; accO[j4*4+1] += pv*v4.y;
                accO[j4*4+2] += pv*v4.z; accO[j4*4+3] += pv*v4.w;
            }
        }
        __syncthreads();
    }
    float linv = 1.0f / sL[row];
    size_t base = ((size_t)(b*Tc + q0 + row))*Hc + cg*16;
    #pragma unroll
    for (int j2 = 0; j2 < 8; j2++) {
        float v0 = accO[j2*2]   * linv;
        float v1 = accO[j2*2+1] * linv;
        __nv_bfloat16 h0 = __float2bfloat16_rn(v0), h1 = __float2bfloat16_rn(v1);
        __nv_bfloat16 l0 = __float2bfloat16_rn(v0 - __bfloat162float(h0));
        __nv_bfloat16 l1 = __float2bfloat16_rn(v1 - __bfloat162float(h1));
        *(__nv_bfloat162*)(g_ahi + base + j2*2) = __nv_bfloat162(h0, h1);
        *(__nv_bfloat162*)(g_alo + base + j2*2) = __nv_bfloat162(l0, l1);
    }
}

// ---------------- warp-MMA grouped O-proj GEMM ----------------
// M=128 tokens, K=128 (A resident: 2 k-halves x hi/lo), N=2048 in 16 chunks of 128 (B dbl-buffered).
__global__ __launch_bounds__(256, 1) void k_oproj_mma(float* __restrict__ out) {
    extern __shared__ char smem[];
    int e = blockIdx.y;
    int cnt = g_cnt[e];
    int m0 = blockIdx.x * 128;
    if (m0 >= cnt) return;

    int* sTok = (int*)smem;
    float* sW = (float*)(smem + 512);
    uint32_t tiles = smem_u32(smem) + 1024;
    int tid = threadIdx.x;

    if (tid < 128) {
        int i = m0 + tid;
        if (i < cnt) { sTok[tid] = g_tok[e*Nc + i]; sW[tid] = g_w[e*Nc + i]; }
        else         { sTok[tid] = -1;               sW[tid] = 0.f; }
    }
    __syncthreads();

    int lrow = tid >> 1;
    int lc0 = (tid & 1) * 4;
    int ltok = sTok[lrow];
    int zf = (ltok >= 0) ? 16 : 0;
    uint32_t loff[4];
    #pragma unroll
    for (int u = 0; u < 4; u++) {
        int c = lc0 + u;
        loff[u] = lrow*128 + ((c ^ (lrow & 7)) << 4);
    }
    // A resident: tiles + (kh*2 + hl)*16384
    {
        const __nv_bfloat16* aH = g_ahi + (size_t)(ltok < 0 ? 0 : ltok)*Hc;
        const __nv_bfloat16* aL = g_alo + (size_t)(ltok < 0 ? 0 : ltok)*Hc;
        #pragma unroll
        for (int kh = 0; kh < 2; kh++) {
            #pragma unroll
            for (int u = 0; u < 4; u++) {
                int c = lc0 + u;
                uint32_t d0 = tiles + kh*32768 + loff[u];
                cpa(d0,         aH + kh*64 + c*8, zf);
                cpa(d0 + 16384, aL + kh*64 + c*8, zf);
            }
        }
        CP_COMMIT;
    }
    const __nv_bfloat16* oH = poh + ((size_t)e*Cc + lrow)*Hc;
    const __nv_bfloat16* oL = pol + ((size_t)e*Cc + lrow)*Hc;
    auto loadB = [&](int nc) {
        uint32_t base = tiles + 65536 + (nc & 1)*65536;
        size_t ro = (size_t)nc*128*Hc;
        #pragma unroll
        for (int kh = 0; kh < 2; kh++) {
            #pragma unroll
            for (int u = 0; u < 4; u++) {
                int c = lc0 + u;
                uint32_t d0 = base + kh*32768 + loff[u];
                cpa(d0,         oH + ro + kh*64 + c*8, 16);
                cpa(d0 + 16384, oL + ro + kh*64 + c*8, 16);
            }
        }
        CP_COMMIT;
    };

    int w = tid >> 5, lane = tid & 31;
    int wr = w & 3, wc = w >> 2;
    int aRow  = wr*32 + (lane & 15);
    int aCB   = lane >> 4;
    int bRowB = wc*64 + (lane & 7) + ((lane >> 4) << 3);
    int bCB   = (lane >> 3) & 1;

    int er0[2], er1[2];
    float ew0[2], ew1[2];
    int et0[2], et1[2];
    #pragma unroll
    for (int mt = 0; mt < 2; mt++) {
        er0[mt] = wr*32 + mt*16 + (lane >> 2);
        er1[mt] = er0[mt] + 8;
        et0[mt] = sTok[er0[mt]]; ew0[mt] = sW[er0[mt]];
        et1[mt] = sTok[er1[mt]]; ew1[mt] = sW[er1[mt]];
    }

    loadB(0);
    for (int nc = 0; nc < 16; nc++) {
        if (nc < 15) {
            loadB(nc + 1);
            asm volatile("cp.async.wait_group 1;" ::: "memory");
        } else {
            asm volatile("cp.async.wait_group 0;" ::: "memory");
        }
        __syncthreads();

        float d[2][8][4];
        #pragma unroll
        for (int mt = 0; mt < 2; mt++)
            #pragma unroll
            for (int nt = 0; nt < 8; nt++)
                #pragma unroll
                for (int q = 0; q < 4; q++) d[mt][nt][q] = 0.f;

        uint32_t bbase = tiles + 65536 + (nc & 1)*65536;
        #pragma unroll
        for (int kh = 0; kh < 2; kh++) {
            #pragma unroll
            for (int kc = 0; kc < 4; kc++) {
                uint32_t ah[2][4], al[2][4];
                #pragma unroll
                for (int mt = 0; mt < 2; mt++) {
                    int r = aRow + mt*16;
                    uint32_t ad = tiles + kh*32768 + r*128 + ((((kc << 1) + aCB) ^ (r & 7)) << 4);
                    ldm4(ah[mt], ad);
                    ldm4(al[mt], ad + 16384);
                }
                #pragma unroll
                for (int np = 0; np < 4; np++) {
                    int r = bRowB + np*16;
                    uint32_t bd = bbase + kh*32768 + r*128 + ((((kc << 1) + bCB) ^ (r & 7)) << 4);
                    uint32_t bh[4], bl[4];
                    ldm4(bh, bd);
                    ldm4(bl, bd + 16384);
                    #pragma unroll
                    for (int mt = 0; mt < 2; mt++) {
                        #pragma unroll
                        for (int i = 0; i < 2; i++) {
                            float* acc = d[mt][np*2 + i];
                            mma16816(acc, ah[mt], bh + 2*i);
                            mma16816(acc, ah[mt], bl + 2*i);
                            mma16816(acc, al[mt], bh + 2*i);
                        }
                    }
                }
            }
        }

        #pragma unroll
        for (int mt = 0; mt < 2; mt++) {
            #pragma unroll
            for (int nt = 0; nt < 8; nt++) {
                int col = nc*128 + wc*64 + nt*8 + (lane & 3)*2;
                if (et0[mt] >= 0) red2(out + (size_t)et0[mt]*Cc + col, d[mt][nt][0]*ew0[mt], d[mt][nt][1]*ew0[mt]);
                if (et1[mt] >= 0) red2(out + (size_t)et1[mt]*Cc + col, d[mt][nt][2]*ew1[mt], d[mt][nt][3]*ew1[mt]);
            }
        }
        __syncthreads();
    }
}

// ---------------- launch ----------------
extern "C" void kernel_launch(void* const* d_in, const int* in_sizes, int n_in,
                              void* d_out, int out_size) {
    const float* x     = (const float*)d_in[0];
    const int*   pid   = (const int*)  d_in[1];
    const float* sim   = (const float*)d_in[2];
    const float* gates = (const float*)d_in[3];
    const float* qp    = (const float*)d_in[4];
    const float* kp    = (const float*)d_in[5];
    const float* vp    = (const float*)d_in[6];
    const float* op    = (const float*)d_in[7];
    float* out = (float*)d_out;

    const int SMEM_QKV = 1024 + 2*65536;            // 132096
    const int SMEM_OP  = 1024 + 65536 + 2*65536;    // 197632
    cudaFuncSetAttribute(k_qkv_mma,   cudaFuncAttributeMaxDynamicSharedMemorySize, SMEM_QKV);
    cudaFuncSetAttribute(k_oproj_mma, cudaFuncAttributeMaxDynamicSharedMemorySize, SMEM_OP);

    k_zero <<<4096, 256>>>(out);
    k_prep <<<1, 512>>>(sim, gates);
    k_gate <<<Nc/GT, 256>>>(x, sim);
    k_convx<<<(Nc*Cc/4)/256, 256>>>(x);
    k_convp<<<dim3(256, Ec, 3), 256>>>(qp, kp, vp);
    k_convo<<<dim3(256, Ec), 256>>>(op);
    k_qkv_mma<<<dim3(Nc/128, Ec, 3), 256, SMEM_QKV>>>();
    k_rope <<<(Nc*64)/256, 256>>>(pid);
    k_attn <<<dim3(Tc/32, Bc), 256>>>();
    k_oproj_mma<<<dim3(Nc/128, Ec), 256, SMEM_OP>>>(out);
}

// round 5
// speedup vs baseline: 6.1783x; 4.2761x over previous
#include <cuda_runtime.h>
#include <cuda_bf16.h>
#include <math.h>
#include <stdint.h>

#define Bc 4
#define Tc 2048
#define Cc 2048
#define Hc 128
#define Ec 16
#define Nc (Bc*Tc)
#define GT 4

// ---------------- device scratch ----------------
__device__ float g_q[Nc*Hc];
__device__ float g_k[Nc*Hc];
__device__ float g_v[Nc*Hc];
__device__ int   g_cnt[Ec];
__device__ int   g_tok[Ec*Nc];
__device__ float g_w[Ec*Nc];
__device__ float g_wninv[Ec];
__device__ float g_sig[Ec];

__device__ __nv_bfloat16 xhi[(size_t)Nc*Cc], xlo[(size_t)Nc*Cc];
__device__ __nv_bfloat16 pqh[(size_t)Ec*Hc*Cc], pql[(size_t)Ec*Hc*Cc];
__device__ __nv_bfloat16 pkh[(size_t)Ec*Hc*Cc], pkl[(size_t)Ec*Hc*Cc];
__device__ __nv_bfloat16 pvh[(size_t)Ec*Hc*Cc], pvl[(size_t)Ec*Hc*Cc];
__device__ __nv_bfloat16 poh[(size_t)Ec*Cc*Hc], pol[(size_t)Ec*Cc*Hc];
__device__ __nv_bfloat16 g_ahi[Nc*Hc], g_alo[Nc*Hc];
// rope outputs, bf16 split
__device__ __nv_bfloat16 qshi[Nc*Hc], qslo[Nc*Hc];
__device__ __nv_bfloat16 kshi[Nc*Hc], kslo[Nc*Hc];
__device__ __nv_bfloat16 vshi[Nc*Hc], vslo[Nc*Hc];

// ---------------- helpers ----------------
__device__ __forceinline__ uint32_t smem_u32(const void* p) {
    uint32_t a;
    asm("{ .reg .u64 t; cvta.to.shared.u64 t, %1; cvt.u32.u64 %0, t; }" : "=r"(a) : "l"(p));
    return a;
}
__device__ __forceinline__ void ldm4(uint32_t* r, uint32_t a) {
    asm volatile("ldmatrix.sync.aligned.m8n8.x4.shared.b16 {%0,%1,%2,%3}, [%4];"
        : "=r"(r[0]), "=r"(r[1]), "=r"(r[2]), "=r"(r[3]) : "r"(a));
}
__device__ __forceinline__ void ldm4t(uint32_t* r, uint32_t a) {
    asm volatile("ldmatrix.sync.aligned.m8n8.x4.trans.shared.b16 {%0,%1,%2,%3}, [%4];"
        : "=r"(r[0]), "=r"(r[1]), "=r"(r[2]), "=r"(r[3]) : "r"(a));
}
__device__ __forceinline__ void mma16816(float* d, const uint32_t* a, const uint32_t* b) {
    asm volatile("mma.sync.aligned.m16n8k16.row.col.f32.bf16.bf16.f32 "
        "{%0,%1,%2,%3},{%4,%5,%6,%7},{%8,%9},{%0,%1,%2,%3};"
        : "+f"(d[0]), "+f"(d[1]), "+f"(d[2]), "+f"(d[3])
        : "r"(a[0]), "r"(a[1]), "r"(a[2]), "r"(a[3]), "r"(b[0]), "r"(b[1]));
}
__device__ __forceinline__ void cpa(uint32_t dst, const void* src, int zf) {
    asm volatile("cp.async.cg.shared.global [%0], [%1], 16, %2;"
        :: "r"(dst), "l"((unsigned long long)__cvta_generic_to_global(src)), "r"(zf) : "memory");
}
__device__ __forceinline__ void red2(float* p, float x, float y) {
    asm volatile("red.global.add.v2.f32 [%0], {%1,%2};"
        :: "l"((unsigned long long)__cvta_generic_to_global(p)), "f"(x), "f"(y) : "memory");
}
__device__ __forceinline__ uint32_t packbf(float a, float b) {
    __nv_bfloat162 t(__float2bfloat16_rn(a), __float2bfloat16_rn(b));
    return *(uint32_t*)&t;
}
#define CP_COMMIT asm volatile("cp.async.commit_group;" ::: "memory")

// ---------------- init: zero + prep merged ----------------
__global__ void k_init(float* __restrict__ out, const float* __restrict__ sim,
                       const float* __restrict__ gates) {
    int i = blockIdx.x * blockDim.x + threadIdx.x;
    int stride = gridDim.x * blockDim.x;
    float4 z = make_float4(0.f, 0.f, 0.f, 0.f);
    for (int j = i; j < Nc*Cc/4; j += stride) ((float4*)out)[j] = z;
    for (int j = i; j < Nc*Hc/4; j += stride) {
        ((float4*)g_q)[j] = z;
        ((float4*)g_k)[j] = z;
        ((float4*)g_v)[j] = z;
    }
    if (i < Ec) g_cnt[i] = 0;
    if (blockIdx.x == gridDim.x - 1) {
        int w = threadIdx.x >> 5, lane = threadIdx.x & 31;
        #pragma unroll
        for (int ee = 0; ee < 2; ee++) {
            int e = w*2 + ee;
            float s = 0.f;
            for (int r = lane; r < Cc; r += 32) {
                float v = sim[(size_t)r*Ec + e];
                s += v*v;
            }
            #pragma unroll
            for (int o = 16; o; o >>= 1) s += __shfl_xor_sync(0xffffffffu, s, o);
            if (lane == 0) g_wninv[e] = 1.0f / fmaxf(sqrtf(s), 1e-12f);
        }
        if (threadIdx.x < Ec) g_sig[threadIdx.x] = 1.0f / (1.0f + expf(-gates[threadIdx.x]));
    }
}

// ---------------- gating ----------------
__global__ void k_gate(const float* __restrict__ x, const float* __restrict__ sim) {
    int n0 = blockIdx.x * GT;
    float dot[GT][Ec];
    float ss[GT];
    #pragma unroll
    for (int j = 0; j < GT; j++) {
        ss[j] = 0.f;
        #pragma unroll
        for (int e = 0; e < Ec; e++) dot[j][e] = 0.f;
    }
    for (int i = threadIdx.x; i < Cc; i += 256) {
        float xv[GT];
        #pragma unroll
        for (int j = 0; j < GT; j++) {
            xv[j] = x[(size_t)(n0 + j)*Cc + i];
            ss[j] += xv[j]*xv[j];
        }
        const float4* s4 = (const float4*)(sim + (size_t)i*Ec);
        #pragma unroll
        for (int q = 0; q < 4; q++) {
            float4 sv = s4[q];
            #pragma unroll
            for (int j = 0; j < GT; j++) {
                dot[j][q*4+0] += xv[j]*sv.x;
                dot[j][q*4+1] += xv[j]*sv.y;
                dot[j][q*4+2] += xv[j]*sv.z;
                dot[j][q*4+3] += xv[j]*sv.w;
            }
        }
    }
    __shared__ float red[8][GT*Ec + GT];
    int wid = threadIdx.x >> 5, lane = threadIdx.x & 31;
    #pragma unroll
    for (int j = 0; j < GT; j++) {
        #pragma unroll
        for (int e = 0; e < Ec; e++) {
            float v = dot[j][e];
            #pragma unroll
            for (int o = 16; o; o >>= 1) v += __shfl_xor_sync(0xffffffffu, v, o);
            if (lane == 0) red[wid][j*Ec + e] = v;
        }
        float v = ss[j];
        #pragma unroll
        for (int o = 16; o; o >>= 1) v += __shfl_xor_sync(0xffffffffu, v, o);
        if (lane == 0) red[wid][GT*Ec + j] = v;
    }
    __syncthreads();
    if (threadIdx.x < GT*Ec + GT) {
        float s = 0.f;
        #pragma unroll
        for (int w = 0; w < 8; w++) s += red[w][threadIdx.x];
        red[0][threadIdx.x] = s;
    }
    __syncthreads();
    if (threadIdx.x < GT) {
        int j = threadIdx.x;
        int n = n0 + j;
        float xin = rsqrtf(fmaxf(red[0][GT*Ec + j], 1e-24f));
        float logitv[Ec], gatedv[Ec];
        int act = 0;
        #pragma unroll
        for (int e = 0; e < Ec; e++) {
            float lg = red[0][j*Ec + e] * xin * g_wninv[e] - g_sig[e];
            logitv[e] = lg;
            gatedv[e] = fmaxf(lg, 0.f);
            act += (lg > 0.f) ? 1 : 0;
        }
        unsigned mask = 0u;
        if (act > 0) {
            #pragma unroll
            for (int e = 0; e < Ec; e++) if (logitv[e] > 0.f) mask |= (1u << e);
        } else {
            int i1 = 0;
            #pragma unroll
            for (int e = 1; e < Ec; e++) if (logitv[e] > logitv[i1]) i1 = e;
            int i2 = (i1 == 0) ? 1 : 0;
            #pragma unroll
            for (int e = 0; e < Ec; e++)
                if (e != i1 && logitv[e] > logitv[i2]) i2 = e;
            mask = (1u << i1) | (1u << i2);
        }
        float m = -1e30f;
        #pragma unroll
        for (int e = 0; e < Ec; e++) if ((mask >> e) & 1u) m = fmaxf(m, gatedv[e]);
        float ssum = 0.f;
        float ex[Ec];
        #pragma unroll
        for (int e = 0; e < Ec; e++) {
            float t = ((mask >> e) & 1u) ? expf(gatedv[e] - m) : 0.f;
            ex[e] = t;
            ssum += t;
        }
        float sinv = 1.f / ssum;
        #pragma unroll
        for (int e = 0; e < Ec; e++) {
            if ((mask >> e) & 1u) {
                int p = atomicAdd(&g_cnt[e], 1);
                g_tok[e*Nc + p] = n;
                g_w[e*Nc + p]   = ex[e] * sinv;
            }
        }
    }
}

// ---------------- merged conversions ----------------
__global__ void k_conv(const float* __restrict__ x,
                       const float* __restrict__ qp, const float* __restrict__ kp,
                       const float* __restrict__ vp, const float* __restrict__ op) {
    int y = blockIdx.y;
    if (y == 4) {   // x -> xhi/xlo
        #pragma unroll
        for (int j = 0; j < 4; j++) {
            int i = (blockIdx.x*4 + j)*256 + threadIdx.x;
            float4 v = ((const float4*)x)[i];
            __nv_bfloat16 h0 = __float2bfloat16_rn(v.x), h1 = __float2bfloat16_rn(v.y);
            __nv_bfloat16 h2 = __float2bfloat16_rn(v.z), h3 = __float2bfloat16_rn(v.w);
            __nv_bfloat16 l0 = __float2bfloat16_rn(v.x - __bfloat162float(h0));
            __nv_bfloat16 l1 = __float2bfloat16_rn(v.y - __bfloat162float(h1));
            __nv_bfloat16 l2 = __float2bfloat16_rn(v.z - __bfloat162float(h2));
            __nv_bfloat16 l3 = __float2bfloat16_rn(v.w - __bfloat162float(h3));
            ((__nv_bfloat162*)xhi)[i*2]   = __nv_bfloat162(h0, h1);
            ((__nv_bfloat162*)xhi)[i*2+1] = __nv_bfloat162(h2, h3);
            ((__nv_bfloat162*)xlo)[i*2]   = __nv_bfloat162(l0, l1);
            ((__nv_bfloat162*)xlo)[i*2+1] = __nv_bfloat162(l2, l3);
        }
        return;
    }
    __shared__ float tile[32][33];
    int e = blockIdx.x >> 8;
    int t = blockIdx.x & 255;
    int c0 = (t >> 2) * 32, h0 = (t & 3) * 32;
    int tx = threadIdx.x & 31, ty = threadIdx.x >> 5;
    if (y < 3) {    // qkv proj: [E][C][H] -> [E][H][C]
        const float* src = (y == 0) ? qp : (y == 1) ? kp : vp;
        __nv_bfloat16* dh = (y == 0) ? pqh : (y == 1) ? pkh : pvh;
        __nv_bfloat16* dl = (y == 0) ? pql : (y == 1) ? pkl : pvl;
        #pragma unroll
        for (int cy = 0; cy < 32; cy += 8)
            tile[ty + cy][tx] = src[((size_t)e*Cc + c0 + ty + cy)*Hc + h0 + tx];
        __syncthreads();
        #pragma unroll
        for (int hy = 0; hy < 32; hy += 8) {
            float v = tile[tx][ty + hy];
            size_t o = ((size_t)e*Hc + h0 + ty + hy)*Cc + c0 + tx;
            __nv_bfloat16 hh = __float2bfloat16_rn(v);
            dh[o] = hh;
            dl[o] = __float2bfloat16_rn(v - __bfloat162float(hh));
        }
    } else {        // o proj: [E][H][C] -> [E][C][H]
        #pragma unroll
        for (int hy = 0; hy < 32; hy += 8)
            tile[ty + hy][tx] = op[((size_t)e*Hc + h0 + ty + hy)*Cc + c0 + tx];
        __syncthreads();
        #pragma unroll
        for (int cy = 0; cy < 32; cy += 8) {
            float v = tile[tx][ty + cy];
            size_t o = ((size_t)e*Cc + c0 + ty + cy)*Hc + h0 + tx;
            __nv_bfloat16 hh = __float2bfloat16_rn(v);
            poh[o] = hh;
            pol[o] = __float2bfloat16_rn(v - __bfloat162float(hh));
        }
    }
}

// ---------------- warp-MMA grouped QKV GEMM (unchanged from R4) ----------------
__global__ __launch_bounds__(256, 1) void k_qkv_mma() {
    extern __shared__ char smem[];
    int e = blockIdx.y;
    int cnt = g_cnt[e];
    int m0 = blockIdx.x * 128;
    if (m0 >= cnt) return;
    const __nv_bfloat16 *BH, *BL;
    float* dst;
    if (blockIdx.z == 0)      { BH = pqh; BL = pql; dst = g_q; }
    else if (blockIdx.z == 1) { BH = pkh; BL = pkl; dst = g_k; }
    else                      { BH = pvh; BL = pvl; dst = g_v; }

    int* sTok = (int*)smem;
    float* sW = (float*)(smem + 512);
    uint32_t tiles = smem_u32(smem) + 1024;
    int tid = threadIdx.x;

    if (tid < 128) {
        int i = m0 + tid;
        if (i < cnt) { sTok[tid] = g_tok[e*Nc + i]; sW[tid] = g_w[e*Nc + i]; }
        else         { sTok[tid] = -1;               sW[tid] = 0.f; }
    }
    __syncthreads();

    int lrow = tid >> 1;
    int lc0 = (tid & 1) * 4;
    int ltok = sTok[lrow];
    int zf = (ltok >= 0) ? 16 : 0;
    const __nv_bfloat16* aH = xhi + (size_t)(ltok < 0 ? 0 : ltok)*Cc;
    const __nv_bfloat16* aL = xlo + (size_t)(ltok < 0 ? 0 : ltok)*Cc;
    const __nv_bfloat16* bH = BH + ((size_t)e*Hc + lrow)*Cc;
    const __nv_bfloat16* bL = BL + ((size_t)e*Hc + lrow)*Cc;
    uint32_t loff[4];
    #pragma unroll
    for (int u = 0; u < 4; u++) {
        int c = lc0 + u;
        loff[u] = lrow*128 + ((c ^ (lrow & 7)) << 4);
    }
    auto loadStage = [&](int s) {
        uint32_t base = tiles + (s & 1) * 65536;
        int k0 = s * 64;
        #pragma unroll
        for (int u = 0; u < 4; u++) {
            int c = lc0 + u;
            uint32_t d0 = base + loff[u];
            cpa(d0,         aH + k0 + c*8, zf);
            cpa(d0 + 16384, aL + k0 + c*8, zf);
            cpa(d0 + 32768, bH + k0 + c*8, 16);
            cpa(d0 + 49152, bL + k0 + c*8, 16);
        }
        CP_COMMIT;
    };

    int w = tid >> 5, lane = tid & 31;
    int wr = w & 3, wc = w >> 2;
    int aRow  = wr*32 + (lane & 15);
    int aCB   = lane >> 4;
    int bRowB = wc*64 + (lane & 7) + ((lane >> 4) << 3);
    int bCB   = (lane >> 3) & 1;

    float d[2][8][4];
    #pragma unroll
    for (int mt = 0; mt < 2; mt++)
        #pragma unroll
        for (int nt = 0; nt < 8; nt++)
            #pragma unroll
            for (int q = 0; q < 4; q++) d[mt][nt][q] = 0.f;

    loadStage(0);
    for (int s = 0; s < 32; s++) {
        if (s < 31) {
            loadStage(s + 1);
            asm volatile("cp.async.wait_group 1;" ::: "memory");
        } else {
            asm volatile("cp.async.wait_group 0;" ::: "memory");
        }
        __syncthreads();
        uint32_t base = tiles + (s & 1) * 65536;
        #pragma unroll
        for (int kc = 0; kc < 4; kc++) {
            uint32_t ah[2][4], al[2][4];
            #pragma unroll
            for (int mt = 0; mt < 2; mt++) {
                int r = aRow + mt*16;
                uint32_t ad = base + r*128 + ((((kc << 1) + aCB) ^ (r & 7)) << 4);
                ldm4(ah[mt], ad);
                ldm4(al[mt], ad + 16384);
            }
            #pragma unroll
            for (int np = 0; np < 4; np++) {
                int r = bRowB + np*16;
                uint32_t bd = base + 32768 + r*128 + ((((kc << 1) + bCB) ^ (r & 7)) << 4);
                uint32_t bh[4], bl[4];
                ldm4(bh, bd);
                ldm4(bl, bd + 16384);
                #pragma unroll
                for (int mt = 0; mt < 2; mt++) {
                    #pragma unroll
                    for (int i = 0; i < 2; i++) {
                        float* acc = d[mt][np*2 + i];
                        mma16816(acc, ah[mt], bh + 2*i);
                        mma16816(acc, ah[mt], bl + 2*i);
                        mma16816(acc, al[mt], bh + 2*i);
                    }
                }
            }
        }
        __syncthreads();
    }

    #pragma unroll
    for (int mt = 0; mt < 2; mt++) {
        int r0 = wr*32 + mt*16 + (lane >> 2);
        int r1 = r0 + 8;
        int t0 = sTok[r0], t1 = sTok[r1];
        float w0 = sW[r0], w1 = sW[r1];
        #pragma unroll
        for (int nt = 0; nt < 8; nt++) {
            int col = wc*64 + nt*8 + (lane & 3)*2;
            if (t0 >= 0) red2(dst + (size_t)t0*Hc + col, d[mt][nt][0]*w0, d[mt][nt][1]*w0);
            if (t1 >= 0) red2(dst + (size_t)t1*Hc + col, d[mt][nt][2]*w1, d[mt][nt][3]*w1);
        }
    }
}

// ---------------- RoPE + bf16 hi/lo split of q,k,v ----------------
__global__ void k_rope(const int* __restrict__ pid) {
    int idx = blockIdx.x * blockDim.x + threadIdx.x;
    if (idx >= Nc*64) return;
    int n = idx >> 6;
    int i = idx & 63;
    int t = pid[n & (Tc - 1)];
    float ang = (float)t * exp2f(-(float)i * (13.28771237954945f / 64.0f));
    float s, c;
    sincosf(ang, &s, &c);
    size_t base = (size_t)n * Hc;
    float q0 = g_q[base + i], q1 = g_q[base + i + 64];
    float k0 = g_k[base + i], k1 = g_k[base + i + 64];
    float v0 = g_v[base + i], v1 = g_v[base + i + 64];
    float qa = q0*c - q1*s, qb = q1*c + q0*s;
    float ka = k0*c - k1*s, kb = k1*c + k0*s;
    __nv_bfloat16 h;
    h = __float2bfloat16_rn(qa); qshi[base+i] = h;    qslo[base+i]    = __float2bfloat16_rn(qa - __bfloat162float(h));
    h = __float2bfloat16_rn(qb); qshi[base+i+64] = h; qslo[base+i+64] = __float2bfloat16_rn(qb - __bfloat162float(h));
    h = __float2bfloat16_rn(ka); kshi[base+i] = h;    kslo[base+i]    = __float2bfloat16_rn(ka - __bfloat162float(h));
    h = __float2bfloat16_rn(kb); kshi[base+i+64] = h; kslo[base+i+64] = __float2bfloat16_rn(kb - __bfloat162float(h));
    h = __float2bfloat16_rn(v0); vshi[base+i] = h;    vslo[base+i]    = __float2bfloat16_rn(v0 - __bfloat162float(h));
    h = __float2bfloat16_rn(v1); vshi[base+i+64] = h; vslo[base+i+64] = __float2bfloat16_rn(v1 - __bfloat162float(h));
}

// ---------------- MMA flash attention ----------------
// BQ=128, BKV=64, 8 warps split M (16 rows each).
// smem: Qh [2][128 rows][128B] 32KB | Ql 32KB | 2 stages x (Kh,Kl,Vh,Vl each [2][64][128B] 16KB) 64KB
__global__ __launch_bounds__(256, 1) void k_attn_mma() {
    extern __shared__ char smem[];
    int qb = blockIdx.x;
    int b  = blockIdx.y;
    int q0 = qb * 128;
    uint32_t sQ = smem_u32(smem);           // Qh at 0, Ql at 32768
    uint32_t sKV = sQ + 65536;              // stage: +(kt&1)*65536
    int tid = threadIdx.x, w = tid >> 5, lane = tid & 31;

    // ---- load Q (hi+lo) ----
    {
        int qrow = tid >> 1;
        int c4 = (tid & 1) * 4;
        const __nv_bfloat16* qh = qshi + ((size_t)(b*Tc + q0 + qrow))*Hc;
        const __nv_bfloat16* ql = qslo + ((size_t)(b*Tc + q0 + qrow))*Hc;
        #pragma unroll
        for (int sub = 0; sub < 2; sub++) {
            #pragma unroll
            for (int u = 0; u < 4; u++) {
                int c = c4 + u;
                uint32_t off = sub*16384 + qrow*128 + ((c ^ (qrow & 7)) << 4);
                cpa(sQ + off,         qh + sub*64 + c*8, 16);
                cpa(sQ + 32768 + off, ql + sub*64 + c*8, 16);
            }
        }
        CP_COMMIT;
    }

    // KV loader role
    int krow = tid >> 2;          // 0..63
    int part = tid & 3;           // 0:Kh 1:Kl 2:Vh 3:Vl
    const __nv_bfloat16* kvsrc =
        (part == 0) ? kshi : (part == 1) ? kslo : (part == 2) ? vshi : vslo;
    auto loadKV = [&](int kt) {
        uint32_t base = sKV + (kt & 1)*65536 + part*16384;
        const __nv_bfloat16* src = kvsrc + ((size_t)(b*Tc + kt*64 + krow))*Hc;
        #pragma unroll
        for (int sub = 0; sub < 2; sub++) {
            #pragma unroll
            for (int c = 0; c < 8; c++) {
                cpa(base + sub*8192 + krow*128 + ((c ^ (krow & 7)) << 4),
                    src + sub*64 + c*8, 16);
            }
        }
        CP_COMMIT;
    };

    const float scale = 0.08838834764831845f;
    float o[16][4];
    #pragma unroll
    for (int nt = 0; nt < 16; nt++)
        #pragma unroll
        for (int q = 0; q < 4; q++) o[nt][q] = 0.f;
    float m0 = -1e30f, m1 = -1e30f, l0 = 0.f, l1 = 0.f;

    int aRow = w*16 + (lane & 15);
    int aCB  = lane >> 4;
    int bRow = (lane & 7) + ((lane >> 4) << 3);
    int bCB  = (lane >> 3) & 1;
    int rowg0 = q0 + w*16 + (lane >> 2);
    int rowg1 = rowg0 + 8;

    int nkt = 2*qb + 2;
    loadKV(0);
    for (int kt = 0; kt < nkt; kt++) {
        if (kt + 1 < nkt) {
            loadKV(kt + 1);
            asm volatile("cp.async.wait_group 1;" ::: "memory");
        } else {
            asm volatile("cp.async.wait_group 0;" ::: "memory");
        }
        __syncthreads();
        uint32_t kbase = sKV + (kt & 1)*65536;

        // ---- S = Q K^T (split bf16, 3 products) ----
        float sAcc[8][4];
        #pragma unroll
        for (int nt = 0; nt < 8; nt++)
            #pragma unroll
            for (int q = 0; q < 4; q++) sAcc[nt][q] = 0.f;
        #pragma unroll
        for (int sub = 0; sub < 2; sub++) {
            #pragma unroll
            for (int kc = 0; kc < 4; kc++) {
                uint32_t ah[4], al[4];
                uint32_t ad = sQ + sub*16384 + aRow*128 + ((((kc << 1) + aCB) ^ (aRow & 7)) << 4);
                ldm4(ah, ad);
                ldm4(al, ad + 32768);
                #pragma unroll
                for (int nb = 0; nb < 4; nb++) {
                    int r = bRow + nb*16;
                    uint32_t bd = kbase + sub*8192 + r*128 + ((((kc << 1) + bCB) ^ (r & 7)) << 4);
                    uint32_t bh[4], bl[4];
                    ldm4(bh, bd);
                    ldm4(bl, bd + 16384);
                    #pragma unroll
                    for (int i = 0; i < 2; i++) {
                        float* acc = sAcc[nb*2 + i];
                        mma16816(acc, ah, bh + 2*i);
                        mma16816(acc, ah, bl + 2*i);
                        mma16816(acc, al, bh + 2*i);
                    }
                }
            }
        }

        // ---- scale + mask ----
        int k0 = kt*64;
        bool diag = (kt >= 2*qb);
        #pragma unroll
        for (int nt = 0; nt < 8; nt++) {
            int cbase = k0 + nt*8 + (lane & 3)*2;
            #pragma unroll
            for (int q = 0; q < 4; q++) {
                float v = sAcc[nt][q] * scale;
                if (diag) {
                    int col = cbase + (q & 1);
                    int row = (q < 2) ? rowg0 : rowg1;
                    if (col > row) v = -1e30f;
                }
                sAcc[nt][q] = v;
            }
        }

        // ---- online softmax ----
        float rm0 = -1e30f, rm1 = -1e30f;
        #pragma unroll
        for (int nt = 0; nt < 8; nt++) {
            rm0 = fmaxf(rm0, fmaxf(sAcc[nt][0], sAcc[nt][1]));
            rm1 = fmaxf(rm1, fmaxf(sAcc[nt][2], sAcc[nt][3]));
        }
        #pragma unroll
        for (int off = 1; off < 4; off <<= 1) {
            rm0 = fmaxf(rm0, __shfl_xor_sync(0xffffffffu, rm0, off));
            rm1 = fmaxf(rm1, __shfl_xor_sync(0xffffffffu, rm1, off));
        }
        float mn0 = fmaxf(m0, rm0), mn1 = fmaxf(m1, rm1);
        float al0 = __expf(m0 - mn0), al1 = __expf(m1 - mn1);
        float ps0 = 0.f, ps1 = 0.f;
        #pragma unroll
        for (int nt = 0; nt < 8; nt++) {
            sAcc[nt][0] = __expf(sAcc[nt][0] - mn0);
            sAcc[nt][1] = __expf(sAcc[nt][1] - mn0);
            sAcc[nt][2] = __expf(sAcc[nt][2] - mn1);
            sAcc[nt][3] = __expf(sAcc[nt][3] - mn1);
            ps0 += sAcc[nt][0] + sAcc[nt][1];
            ps1 += sAcc[nt][2] + sAcc[nt][3];
        }
        #pragma unroll
        for (int off = 1; off < 4; off <<= 1) {
            ps0 += __shfl_xor_sync(0xffffffffu, ps0, off);
            ps1 += __shfl_xor_sync(0xffffffffu, ps1, off);
        }
        l0 = l0*al0 + ps0;
        l1 = l1*al1 + ps1;
        m0 = mn0;
        m1 = mn1;
        #pragma unroll
        for (int nt = 0; nt < 16; nt++) {
            o[nt][0] *= al0; o[nt][1] *= al0;
            o[nt][2] *= al1; o[nt][3] *= al1;
        }

        // ---- O += P V (P split hi/lo) ----
        #pragma unroll
        for (int ks = 0; ks < 4; ks++) {
            uint32_t ph[4], pl[4];
            #pragma unroll
            for (int hq = 0; hq < 2; hq++) {     // two n8 tiles -> a0/a1 and a2/a3
                int nt = 2*ks + hq;
                float p0 = sAcc[nt][0], p1 = sAcc[nt][1];
                float p2 = sAcc[nt][2], p3 = sAcc[nt][3];
                __nv_bfloat16 b0 = __float2bfloat16_rn(p0), b1 = __float2bfloat16_rn(p1);
                __nv_bfloat16 b2 = __float2bfloat16_rn(p2), b3 = __float2bfloat16_rn(p3);
                __nv_bfloat162 hh01(b0, b1), hh23(b2, b3);
                ph[hq*1 + 0 + (hq?1:0)] = 0; // placeholder overwritten below
                ph[0 + hq*2] = *(uint32_t*)&hh01;   // a0 (hq=0) / a2 (hq=1)
                ph[1 + hq*2] = *(uint32_t*)&hh23;   // a1 / a3
                __nv_bfloat162 ll01(__float2bfloat16_rn(p0 - __bfloat162float(b0)),
                                    __float2bfloat16_rn(p1 - __bfloat162float(b1)));
                __nv_bfloat162 ll23(__float2bfloat16_rn(p2 - __bfloat162float(b2)),
                                    __float2bfloat16_rn(p3 - __bfloat162float(b3)));
                pl[0 + hq*2] = *(uint32_t*)&ll01;
                pl[1 + hq*2] = *(uint32_t*)&ll23;
            }
            // fix ordering: a = {a0,a1,a2,a3} = {hq0(c01), hq0(c23), hq1(c01), hq1(c23)} — done above
            int vrow = ks*16 + (lane & 15);
            #pragma unroll
            for (int ht = 0; ht < 8; ht++) {
                int sub = ht >> 2;
                int cloc = (ht & 3)*2 + (lane >> 4);
                uint32_t vd = kbase + 32768 + sub*8192 + vrow*128 + ((cloc ^ (vrow & 7)) << 4);
                uint32_t vh[4], vl[4];
                ldm4t(vh, vd);
                ldm4t(vl, vd + 16384);
                #pragma unroll
                for (int i = 0; i < 2; i++) {
                    float* acc = o[ht*2 + i];
                    mma16816(acc, ph, vh + 2*i);
                    mma16816(acc, ph, vl + 2*i);
                    mma16816(acc, pl, vh + 2*i);
                }
            }
        }
        __syncthreads();
    }

    // ---- epilogue: normalize, emit bf16 hi/lo for oproj ----
    float li0 = 1.0f / l0, li1 = 1.0f / l1;
    size_t ga0 = ((size_t)(b*Tc) + rowg0)*Hc;
    size_t ga1 = ((size_t)(b*Tc) + rowg1)*Hc;
    #pragma unroll
    for (int nt = 0; nt < 16; nt++) {
        int col = nt*8 + (lane & 3)*2;
        float v0 = o[nt][0]*li0, v1 = o[nt][1]*li0;
        float v2 = o[nt][2]*li1, v3 = o[nt][3]*li1;
        __nv_bfloat16 h0 = __float2bfloat16_rn(v0), h1 = __float2bfloat16_rn(v1);
        __nv_bfloat16 h2 = __float2bfloat16_rn(v2), h3 = __float2bfloat16_rn(v3);
        __nv_bfloat162 p01(h0, h1), p23(h2, h3);
        *(__nv_bfloat162*)(g_ahi + ga0 + col) = p01;
        *(__nv_bfloat162*)(g_ahi + ga1 + col) = p23;
        __nv_bfloat162 q01(__float2bfloat16_rn(v0 - __bfloat162float(h0)),
                           __float2bfloat16_rn(v1 - __bfloat162float(h1)));
        __nv_bfloat162 q23(__float2bfloat16_rn(v2 - __bfloat162float(h2)),
                           __float2bfloat16_rn(v3 - __bfloat162float(h3)));
        *(__nv_bfloat162*)(g_alo + ga0 + col) = q01;
        *(__nv_bfloat162*)(g_alo + ga1 + col) = q23;
    }
}

// ---------------- warp-MMA grouped O-proj GEMM (unchanged from R4) ----------------
__global__ __launch_bounds__(256, 1) void k_oproj_mma(float* __restrict__ out) {
    extern __shared__ char smem[];
    int e = blockIdx.y;
    int cnt = g_cnt[e];
    int m0 = blockIdx.x * 128;
    if (m0 >= cnt) return;

    int* sTok = (int*)smem;
    float* sW = (float*)(smem + 512);
    uint32_t tiles = smem_u32(smem) + 1024;
    int tid = threadIdx.x;

    if (tid < 128) {
        int i = m0 + tid;
        if (i < cnt) { sTok[tid] = g_tok[e*Nc + i]; sW[tid] = g_w[e*Nc + i]; }
        else         { sTok[tid] = -1;               sW[tid] = 0.f; }
    }
    __syncthreads();

    int lrow = tid >> 1;
    int lc0 = (tid & 1) * 4;
    int ltok = sTok[lrow];
    int zf = (ltok >= 0) ? 16 : 0;
    uint32_t loff[4];
    #pragma unroll
    for (int u = 0; u < 4; u++) {
        int c = lc0 + u;
        loff[u] = lrow*128 + ((c ^ (lrow & 7)) << 4);
    }
    {
        const __nv_bfloat16* aH = g_ahi + (size_t)(ltok < 0 ? 0 : ltok)*Hc;
        const __nv_bfloat16* aL = g_alo + (size_t)(ltok < 0 ? 0 : ltok)*Hc;
        #pragma unroll
        for (int kh = 0; kh < 2; kh++) {
            #pragma unroll
            for (int u = 0; u < 4; u++) {
                int c = lc0 + u;
                uint32_t d0 = tiles + kh*32768 + loff[u];
                cpa(d0,         aH + kh*64 + c*8, zf);
                cpa(d0 + 16384, aL + kh*64 + c*8, zf);
            }
        }
        CP_COMMIT;
    }
    const __nv_bfloat16* oH = poh + ((size_t)e*Cc + lrow)*Hc;
    const __nv_bfloat16* oL = pol + ((size_t)e*Cc + lrow)*Hc;
    auto loadB = [&](int nc) {
        uint32_t base = tiles + 65536 + (nc & 1)*65536;
        size_t ro = (size_t)nc*128*Hc;
        #pragma unroll
        for (int kh = 0; kh < 2; kh++) {
            #pragma unroll
            for (int u = 0; u < 4; u++) {
                int c = lc0 + u;
                uint32_t d0 = base + kh*32768 + loff[u];
                cpa(d0,         oH + ro + kh*64 + c*8, 16);
                cpa(d0 + 16384, oL + ro + kh*64 + c*8, 16);
            }
        }
        CP_COMMIT;
    };

    int w = tid >> 5, lane = tid & 31;
    int wr = w & 3, wc = w >> 2;
    int aRow  = wr*32 + (lane & 15);
    int aCB   = lane >> 4;
    int bRowB = wc*64 + (lane & 7) + ((lane >> 4) << 3);
    int bCB   = (lane >> 3) & 1;

    int et0[2], et1[2];
    float ew0[2], ew1[2];
    #pragma unroll
    for (int mt = 0; mt < 2; mt++) {
        int r0 = wr*32 + mt*16 + (lane >> 2);
        et0[mt] = sTok[r0]; ew0[mt] = sW[r0];
        et1[mt] = sTok[r0 + 8]; ew1[mt] = sW[r0 + 8];
    }

    loadB(0);
    for (int nc = 0; nc < 16; nc++) {
        if (nc < 15) {
            loadB(nc + 1);
            asm volatile("cp.async.wait_group 1;" ::: "memory");
        } else {
            asm volatile("cp.async.wait_group 0;" ::: "memory");
        }
        __syncthreads();

        float d[2][8][4];
        #pragma unroll
        for (int mt = 0; mt < 2; mt++)
            #pragma unroll
            for (int nt = 0; nt < 8; nt++)
                #pragma unroll
                for (int q = 0; q < 4; q++) d[mt][nt][q] = 0.f;

        uint32_t bbase = tiles + 65536 + (nc & 1)*65536;
        #pragma unroll
        for (int kh = 0; kh < 2; kh++) {
            #pragma unroll
            for (int kc = 0; kc < 4; kc++) {
                uint32_t ah[2][4], al[2][4];
                #pragma unroll
                for (int mt = 0; mt < 2; mt++) {
                    int r = aRow + mt*16;
                    uint32_t ad = tiles + kh*32768 + r*128 + ((((kc << 1) + aCB) ^ (r & 7)) << 4);
                    ldm4(ah[mt], ad);
                    ldm4(al[mt], ad + 16384);
                }
                #pragma unroll
                for (int np = 0; np < 4; np++) {
                    int r = bRowB + np*16;
                    uint32_t bd = bbase + kh*32768 + r*128 + ((((kc << 1) + bCB) ^ (r & 7)) << 4);
                    uint32_t bh[4], bl[4];
                    ldm4(bh, bd);
                    ldm4(bl, bd + 16384);
                    #pragma unroll
                    for (int mt = 0; mt < 2; mt++) {
                        #pragma unroll
                        for (int i = 0; i < 2; i++) {
                            float* acc = d[mt][np*2 + i];
                            mma16816(acc, ah[mt], bh + 2*i);
                            mma16816(acc, ah[mt], bl + 2*i);
                            mma16816(acc, al[mt], bh + 2*i);
                        }
                    }
                }
            }
        }

        #pragma unroll
        for (int mt = 0; mt < 2; mt++) {
            #pragma unroll
            for (int nt = 0; nt < 8; nt++) {
                int col = nc*128 + wc*64 + nt*8 + (lane & 3)*2;
                if (et0[mt] >= 0) red2(out + (size_t)et0[mt]*Cc + col, d[mt][nt][0]*ew0[mt], d[mt][nt][1]*ew0[mt]);
                if (et1[mt] >= 0) red2(out + (size_t)et1[mt]*Cc + col, d[mt][nt][2]*ew1[mt], d[mt][nt][3]*ew1[mt]);
            }
        }
        __syncthreads();
    }
}

// ---------------- launch ----------------
extern "C" void kernel_launch(void* const* d_in, const int* in_sizes, int n_in,
                              void* d_out, int out_size) {
    const float* x     = (const float*)d_in[0];
    const int*   pid   = (const int*)  d_in[1];
    const float* sim   = (const float*)d_in[2];
    const float* gates = (const float*)d_in[3];
    const float* qp    = (const float*)d_in[4];
    const float* kp    = (const float*)d_in[5];
    const float* vp    = (const float*)d_in[6];
    const float* op    = (const float*)d_in[7];
    float* out = (float*)d_out;

    const int SMEM_QKV  = 1024 + 2*65536;            // 132096
    const int SMEM_OP   = 1024 + 65536 + 2*65536;    // 197632
    const int SMEM_ATTN = 65536 + 2*65536;           // 196608
    cudaFuncSetAttribute(k_qkv_mma,   cudaFuncAttributeMaxDynamicSharedMemorySize, SMEM_QKV);
    cudaFuncSetAttribute(k_oproj_mma, cudaFuncAttributeMaxDynamicSharedMemorySize, SMEM_OP);
    cudaFuncSetAttribute(k_attn_mma,  cudaFuncAttributeMaxDynamicSharedMemorySize, SMEM_ATTN);

    k_init <<<4096, 256>>>(out, sim, gates);
    k_gate <<<Nc/GT, 256>>>(x, sim);
    k_conv <<<dim3(4096, 5), 256>>>(x, qp, kp, vp, op);
    k_qkv_mma<<<dim3(Nc/128, Ec, 3), 256, SMEM_QKV>>>();   // profiled (launch idx 3)
    k_rope <<<(Nc*64)/256, 256>>>(pid);
    k_attn_mma<<<dim3(Tc/128, Bc), 256, SMEM_ATTN>>>();
    k_oproj_mma<<<dim3(Nc/128, Ec), 256, SMEM_OP>>>(out);
}